// round 11
// baseline (speedup 1.0000x reference)
#include <cuda_runtime.h>
#include <cstdint>
#include <math.h>

#define DIM     256
#define HEADS   8
#define HDIM    32
#define GW      64
#define HW      56
#define NPIX    3136            // 56*56
#define BATCH   16
#define NTOK    (BATCH * NPIX)  // 50176
#define HIDDEN  1024
#define LN_EPS  1e-6f
#define BN_EPS  1e-3f
#define L2_EPS  1e-12f
#define SCALE_Q 0.17677669529663689f  // 32^-0.5
#define NSPLIT  14                     // 3136 = 14 * 224

// ---------------- scratch (static device globals; no cudaMalloc) -------------
__device__ __align__(16) float d_dwconv   [NTOK * DIM];
__device__ __align__(16) float d_norm1    [NTOK * DIM];
__device__ __align__(16) float d_qT       [BATCH * HEADS * HDIM * NPIX]; // [b][h][d][n]
__device__ __align__(16) float d_kT       [BATCH * HEADS * HDIM * NPIX]; // [b][h][e][n]
__device__ __align__(16) float d_v        [NTOK * DIM];
__device__ __align__(16) float d_attn_part[NSPLIT * BATCH * HEADS * HDIM * HDIM];
__device__ __align__(16) float d_wbT      [BATCH * DIM * DIM];   // [b][n=c][k=h*32+d]
__device__ __align__(16) float d_merged   [NTOK * DIM];
__device__ __align__(16) float d_h1       [NTOK * HIDDEN];
__device__ __align__(16) float d_qkvT     [768 * 256];
__device__ __align__(16) float d_fc1T     [1024 * 256];
__device__ __align__(16) float d_fc2T     [256 * 1024];

// ---------------- PTX helpers -------------------------------------------------
__device__ __forceinline__ void cp_async16_s(uint32_t saddr, const void* gptr) {
    asm volatile("cp.async.cg.shared.global [%0], [%1], 16;\n" :: "r"(saddr), "l"(gptr));
}
__device__ __forceinline__ void cp_commit() { asm volatile("cp.async.commit_group;\n"); }

__device__ __forceinline__ void ldsm_x4(uint32_t r[4], uint32_t addr) {
    asm volatile("ldmatrix.sync.aligned.m8n8.x4.shared.b16 {%0,%1,%2,%3}, [%4];"
        : "=r"(r[0]), "=r"(r[1]), "=r"(r[2]), "=r"(r[3]) : "r"(addr));
}
__device__ __forceinline__ void mma_tf32(float c[4], const uint32_t a[4],
                                         uint32_t b0, uint32_t b1) {
    asm volatile(
        "mma.sync.aligned.m16n8k8.row.col.f32.tf32.tf32.f32 "
        "{%0,%1,%2,%3}, {%4,%5,%6,%7}, {%8,%9}, {%0,%1,%2,%3};"
        : "+f"(c[0]), "+f"(c[1]), "+f"(c[2]), "+f"(c[3])
        : "r"(a[0]), "r"(a[1]), "r"(a[2]), "r"(a[3]), "r"(b0), "r"(b1));
}

// ---------------- kernel 0: transpose weights -> [N, K] fp32 ------------------
__global__ void __launch_bounds__(256) transpose3_kernel(
    const float* __restrict__ qkv_w, const float* __restrict__ fc1_w,
    const float* __restrict__ fc2_w)
{
    const float* src; float* dst; int R, C;
    if (blockIdx.z == 0)      { src = qkv_w; dst = d_qkvT; R = 256;  C = 768;  }
    else if (blockIdx.z == 1) { src = fc1_w; dst = d_fc1T; R = 256;  C = 1024; }
    else                      { src = fc2_w; dst = d_fc2T; R = 1024; C = 256;  }
    int x0 = blockIdx.x * 32, y0 = blockIdx.y * 32;
    if (x0 >= C || y0 >= R) return;

    __shared__ float t[32][33];
    int tx = threadIdx.x & 31, ty = threadIdx.x >> 5;   // 32 x 8
    #pragma unroll
    for (int i = ty; i < 32; i += 8)
        t[i][tx] = src[(size_t)(y0 + i) * C + x0 + tx];
    __syncthreads();
    #pragma unroll
    for (int i = ty; i < 32; i += 8)
        dst[(size_t)(x0 + i) * R + y0 + tx] = t[tx][i];
}

// ---- kernel 1: dwconv3x3 + group cumsum + LayerNorm, warp-per-pixel ---------
__global__ void __launch_bounds__(256) dwln_kernel(
    const float* __restrict__ x, const float* __restrict__ dwk,
    const float* __restrict__ dwb, const float* __restrict__ g,
    const float* __restrict__ be)
{
    const int lane = threadIdx.x & 31;
    const int wrp  = threadIdx.x >> 5;
    const int pix  = blockIdx.x * 8 + wrp;
    const int b  = pix / NPIX;
    const int p  = pix - b * NPIX;
    const int hh = p / HW, ww = p - hh * HW;
    const int c  = lane * 8;

    float val[8];
    if (lane < 8) {
        float4 a0 = *(const float4*)&x[(size_t)pix * DIM + c];
        float4 a1 = *(const float4*)&x[(size_t)pix * DIM + c + 4];
        val[0]=a0.x; val[1]=a0.y; val[2]=a0.z; val[3]=a0.w;
        val[4]=a1.x; val[5]=a1.y; val[6]=a1.z; val[7]=a1.w;
    } else {
        const int cc = c - GW;
        float4 b0 = *(const float4*)&dwb[cc];
        float4 b1 = *(const float4*)&dwb[cc + 4];
        val[0]=b0.x; val[1]=b0.y; val[2]=b0.z; val[3]=b0.w;
        val[4]=b1.x; val[5]=b1.y; val[6]=b1.z; val[7]=b1.w;
        #pragma unroll
        for (int ky = 0; ky < 3; ky++) {
            int hy = hh + ky - 1;
            if ((unsigned)hy < (unsigned)HW) {
                #pragma unroll
                for (int kx = 0; kx < 3; kx++) {
                    int wx = ww + kx - 1;
                    if ((unsigned)wx < (unsigned)HW) {
                        const float* xp = &x[((size_t)(b * HW + hy) * HW + wx) * DIM + c];
                        const float* wp = &dwk[(ky * 3 + kx) * 192 + cc];
                        float4 x0 = *(const float4*)xp, x1 = *(const float4*)(xp + 4);
                        float4 w0 = *(const float4*)wp, w1 = *(const float4*)(wp + 4);
                        val[0] += x0.x * w0.x; val[1] += x0.y * w0.y;
                        val[2] += x0.z * w0.z; val[3] += x0.w * w0.w;
                        val[4] += x1.x * w1.x; val[5] += x1.y * w1.y;
                        val[6] += x1.z * w1.z; val[7] += x1.w * w1.w;
                    }
                }
            }
        }
    }

    {
        const int s0 = 8 + (lane & 7);
        const int gi = (lane >> 3) - 1;
        #pragma unroll
        for (int i = 0; i < 8; i++) {
            float k0 = __shfl_sync(0xffffffffu, val[i], s0);
            float k1 = __shfl_sync(0xffffffffu, val[i], s0 + 8);
            float k2 = __shfl_sync(0xffffffffu, val[i], s0 + 16);
            if (lane >= 8) {
                float s = k0;
                if (gi >= 1) s += k1;
                if (gi >= 2) s += k2;
                val[i] = s;
            }
        }
    }

    float sum = 0.f;
    #pragma unroll
    for (int i = 0; i < 8; i++) sum += val[i];
    #pragma unroll
    for (int o = 16; o; o >>= 1) sum += __shfl_xor_sync(0xffffffffu, sum, o);
    float mean = sum * (1.0f / 256.0f);

    float ss = 0.f;
    #pragma unroll
    for (int i = 0; i < 8; i++) { float d = val[i] - mean; ss += d * d; }
    #pragma unroll
    for (int o = 16; o; o >>= 1) ss += __shfl_xor_sync(0xffffffffu, ss, o);
    float rstd = rsqrtf(ss * (1.0f / 256.0f) + LN_EPS);

    float4 g0 = *(const float4*)&g[c],  g1 = *(const float4*)&g[c + 4];
    float4 e0 = *(const float4*)&be[c], e1 = *(const float4*)&be[c + 4];
    *(float4*)&d_dwconv[(size_t)pix * DIM + c]     = make_float4(val[0], val[1], val[2], val[3]);
    *(float4*)&d_dwconv[(size_t)pix * DIM + c + 4] = make_float4(val[4], val[5], val[6], val[7]);
    float4 n0 = make_float4((val[0]-mean)*rstd*g0.x+e0.x, (val[1]-mean)*rstd*g0.y+e0.y,
                            (val[2]-mean)*rstd*g0.z+e0.z, (val[3]-mean)*rstd*g0.w+e0.w);
    float4 n1 = make_float4((val[4]-mean)*rstd*g1.x+e1.x, (val[5]-mean)*rstd*g1.y+e1.y,
                            (val[6]-mean)*rstd*g1.z+e1.z, (val[7]-mean)*rstd*g1.w+e1.w);
    *(float4*)&d_norm1[(size_t)pix * DIM + c]     = n0;
    *(float4*)&d_norm1[(size_t)pix * DIM + c + 4] = n1;
}

// -------- tf32 mma.sync GEMM v4: BM=256, BN=128, 1 CTA/SM, warp tile 64x64 ----
// 8 warps as (wm 0..3) x (wn 0..1). Single-barrier 3-stage cp.async pipeline.
// MODE 1: BN( +bias +add1 )   MODE 2: gelu(+bias)   MODE 3: +bias +add1
// MODE 4: qkv epilogue: per-head l2norm; q,k -> transposed globals, v -> dense.
#define TG_BOFF  98304                 // A: 3 x 32KB, B: 3 x 16KB
#define TG_SMEM  147456

template<int KDIM, int MODE, bool PERBATCH>
__global__ void __launch_bounds__(256, 1)
tgemm2(const float* __restrict__ A, int lda,
       const float* __restrict__ Bt,
       float* __restrict__ C, int ldc, int m_off,
       const float* __restrict__ bias, const float* __restrict__ add1,
       const float* __restrict__ bn_g, const float* __restrict__ bn_b,
       const float* __restrict__ bn_m, const float* __restrict__ bn_v)
{
    extern __shared__ char smem[];
    const uint32_t sb = (uint32_t)__cvta_generic_to_shared(smem);
    const int tid  = threadIdx.x;
    const int lane = tid & 31;
    const int w    = tid >> 5;
    const int wm   = w >> 1;      // 0..3
    const int wn   = w & 1;       // 0..1

    int m0, mrows;
    if (PERBATCH) {
        int batch = blockIdx.y / 13;
        int bt    = blockIdx.y % 13;
        m0 = batch * NPIX + bt * 256;
        mrows = min(256, NPIX - bt * 256);
    } else {
        m0 = m_off + blockIdx.y * 256; mrows = 256;
    }
    const int n0 = blockIdx.x * 128;
    const float* Bp = PERBATCH ? (Bt + (size_t)(blockIdx.y / 13) * 65536) : Bt;

    float acc[4][8][4];
    #pragma unroll
    for (int mi = 0; mi < 4; mi++)
        #pragma unroll
        for (int ni = 0; ni < 8; ni++)
            #pragma unroll
            for (int q = 0; q < 4; q++) acc[mi][ni][q] = 0.f;

    auto load_stage = [&](int st) {
        int slot = st % 3;
        int k0 = st * 32;
        #pragma unroll
        for (int i = 0; i < 8; i++) {
            int lin = tid + 256 * i;          // 0..2047
            int r = lin >> 3, ch = lin & 7;
            int rg = m0 + (r < mrows ? r : mrows - 1);
            cp_async16_s(sb + slot * 32768 + r * 128 + ((ch ^ (r & 7)) << 4),
                         A + (size_t)rg * lda + k0 + ch * 4);
        }
        #pragma unroll
        for (int i = 0; i < 4; i++) {
            int lin = tid + 256 * i;          // 0..1023
            int r = lin >> 3, ch = lin & 7;
            cp_async16_s(sb + TG_BOFF + slot * 16384 + r * 128 + ((ch ^ (r & 7)) << 4),
                         Bp + (size_t)(n0 + r) * KDIM + k0 + ch * 4);
        }
        cp_commit();
    };

    const int KT = KDIM / 32;
    load_stage(0); load_stage(1);

    const int arow_l = (lane & 7) + ((lane >> 3) & 1) * 8;
    const int akoff  = lane >> 4;
    const int brow_l = (lane & 7) + (lane >> 4) * 8;
    const int bkoff  = (lane >> 3) & 1;
    const int sx     = lane & 7;

    for (int s = 0; s < KT; s++) {
        int slot = s % 3;
        if (s < KT - 1) asm volatile("cp.async.wait_group 1;\n" ::: "memory");
        else            asm volatile("cp.async.wait_group 0;\n" ::: "memory");
        __syncthreads();
        if (s + 2 < KT) load_stage(s + 2);

        uint32_t aBase = sb + slot * 32768 + (wm * 64) * 128;
        uint32_t bBase = sb + TG_BOFF + slot * 16384 + (wn * 64) * 128;

        #pragma unroll
        for (int kc = 0; kc < 4; kc++) {
            uint32_t a[4][4];
            #pragma unroll
            for (int mi = 0; mi < 4; mi++)
                ldsm_x4(a[mi], aBase + (mi * 16 + arow_l) * 128
                               + (((2 * kc + akoff) ^ sx) << 4));
            uint32_t bf[4][4];
            #pragma unroll
            for (int nj = 0; nj < 4; nj++)
                ldsm_x4(bf[nj], bBase + (nj * 16 + brow_l) * 128
                                + (((2 * kc + bkoff) ^ sx) << 4));
            #pragma unroll
            for (int mi = 0; mi < 4; mi++)
                #pragma unroll
                for (int ni = 0; ni < 8; ni++)
                    mma_tf32(acc[mi][ni], a[mi],
                             bf[ni >> 1][(ni & 1) * 2], bf[ni >> 1][(ni & 1) * 2 + 1]);
        }
    }

    // ---- MODE 4 q/k path: per-head l2norm (warp spans TWO heads), smem stage,
    //      coalesced transposed store ----
    if (MODE == 4 && n0 < 512) {
        float* sT = (float*)smem;             // [col 128][row 256], stride 260
        __syncthreads();
        #pragma unroll
        for (int mi = 0; mi < 4; mi++) {
            #pragma unroll
            for (int h = 0; h < 2; h++) {
                float ssA = 0.f, ssB = 0.f;
                #pragma unroll
                for (int ni = 0; ni < 4; ni++) {
                    float v0 = acc[mi][ni][2 * h], v1 = acc[mi][ni][2 * h + 1];
                    ssA += v0 * v0 + v1 * v1;
                }
                #pragma unroll
                for (int ni = 4; ni < 8; ni++) {
                    float v0 = acc[mi][ni][2 * h], v1 = acc[mi][ni][2 * h + 1];
                    ssB += v0 * v0 + v1 * v1;
                }
                ssA += __shfl_xor_sync(0xffffffffu, ssA, 1);
                ssA += __shfl_xor_sync(0xffffffffu, ssA, 2);
                ssB += __shfl_xor_sync(0xffffffffu, ssB, 1);
                ssB += __shfl_xor_sync(0xffffffffu, ssB, 2);
                float scA = rsqrtf(fmaxf(ssA, L2_EPS));
                float scB = rsqrtf(fmaxf(ssB, L2_EPS));
                if (n0 < 256) { scA *= SCALE_Q; scB *= SCALE_Q; }

                int rowl = wm * 64 + mi * 16 + (lane >> 2) + h * 8;
                #pragma unroll
                for (int ni = 0; ni < 8; ni++) {
                    float sc = (ni < 4) ? scA : scB;
                    int dl = wn * 64 + ni * 8 + (lane & 3) * 2;
                    sT[dl * 260 + rowl]       = acc[mi][ni][2 * h] * sc;
                    sT[(dl + 1) * 260 + rowl] = acc[mi][ni][2 * h + 1] * sc;
                }
            }
        }
        __syncthreads();
        float* dstT = (n0 < 256) ? d_qT : d_kT;
        #pragma unroll
        for (int i = 0; i < 32; i++) {
            int idx = tid + i * 256;          // 0..8191
            int cl  = idx >> 6;               // 0..127
            int row = (idx & 63) * 4;         // 0..252
            int grow = m0 + row;
            int bb = grow / NPIX;
            int n  = grow - bb * NPIX;        // float4 never straddles batch (3136%4==0)
            int gcol = n0 + cl;
            int head = (gcol & 255) >> 5;
            int d    = gcol & 31;
            float4 v4 = *(float4*)&sT[cl * 260 + row];
            *(float4*)&dstT[((size_t)(bb * 8 + head) * 32 + d) * NPIX + n] = v4;
        }
        return;
    }

    // ---- epilogue (register-resident) ----
    #pragma unroll
    for (int mi = 0; mi < 4; mi++) {
        #pragma unroll
        for (int h = 0; h < 2; h++) {
            int lr = wm * 64 + mi * 16 + (lane >> 2) + h * 8;
            if (PERBATCH && lr >= mrows) continue;
            size_t grow = (size_t)(m0 + lr);

            #pragma unroll
            for (int ni = 0; ni < 8; ni++) {
                float v0 = acc[mi][ni][2 * h], v1 = acc[mi][ni][2 * h + 1];
                if (MODE == 4) {
                    int gc = (n0 - 512) + wn * 64 + ni * 8 + (lane & 3) * 2;
                    *(float2*)&C[grow * ldc + gc] = make_float2(v0, v1);
                    continue;
                }
                int gc = n0 + wn * 64 + ni * 8 + (lane & 3) * 2;
                if (MODE == 1) {
                    float2 ad = *(const float2*)&add1[grow * 256 + gc];
                    v0 += bias[gc]     + ad.x;
                    v1 += bias[gc + 1] + ad.y;
                    v0 = (v0 - bn_m[gc    ]) * rsqrtf(bn_v[gc    ] + BN_EPS) * bn_g[gc    ] + bn_b[gc    ];
                    v1 = (v1 - bn_m[gc + 1]) * rsqrtf(bn_v[gc + 1] + BN_EPS) * bn_g[gc + 1] + bn_b[gc + 1];
                } else if (MODE == 2) {
                    v0 += bias[gc];   v1 += bias[gc + 1];
                    v0 = 0.5f * v0 * (1.0f + erff(v0 * 0.70710678118654752f));
                    v1 = 0.5f * v1 * (1.0f + erff(v1 * 0.70710678118654752f));
                } else if (MODE == 3) {
                    float2 ad = *(const float2*)&add1[grow * 256 + gc];
                    v0 += bias[gc]     + ad.x;
                    v1 += bias[gc + 1] + ad.y;
                }
                *(float2*)&C[grow * ldc + gc] = make_float2(v0, v1);
            }
        }
    }
}

// ------- attn split-K: per (b,h,split) partial 32x32 q^T k via tf32 mma ------
#define AS_SMEM 24576   // 3 stages x 8KB

__global__ void __launch_bounds__(256) attn_split_kernel()
{
    extern __shared__ char smem[];
    const uint32_t sb = (uint32_t)__cvta_generic_to_shared(smem);
    const int bh = blockIdx.x;
    const int split = blockIdx.y;
    const int tid = threadIdx.x, lane = tid & 31, w = tid >> 5;
    const int wm = w >> 2, wn = w & 3;

    const float* qT = d_qT + (size_t)bh * 32 * NPIX + split * 224;
    const float* kT = d_kT + (size_t)bh * 32 * NPIX + split * 224;

    float c[4] = {0.f, 0.f, 0.f, 0.f};

    auto load_stage = [&](int st) {
        int slot = st % 3;
        int k0 = st * 32;
        int r = tid >> 3, ch = tid & 7;
        uint32_t dst = sb + slot * 8192 + r * 128 + ((ch ^ (r & 7)) << 4);
        cp_async16_s(dst,        qT + (size_t)r * NPIX + k0 + ch * 4);
        cp_async16_s(dst + 4096, kT + (size_t)r * NPIX + k0 + ch * 4);
        cp_commit();
    };

    const int KT = 7;
    load_stage(0); load_stage(1);

    const int arow_l = (lane & 7) + ((lane >> 3) & 1) * 8;
    const int akoff  = lane >> 4;
    const int brow_l = (lane & 7) + (lane >> 4) * 8;
    const int bkoff  = (lane >> 3) & 1;
    const int sx     = lane & 7;
    const int nj     = wn >> 1;
    const int nsel   = (wn & 1) * 2;

    for (int s = 0; s < KT; s++) {
        int slot = s % 3;
        if (s < KT - 1) asm volatile("cp.async.wait_group 1;\n" ::: "memory");
        else            asm volatile("cp.async.wait_group 0;\n" ::: "memory");
        __syncthreads();
        if (s + 2 < KT) load_stage(s + 2);

        uint32_t aBase = sb + slot * 8192 + (wm * 16) * 128;
        uint32_t bBase = sb + slot * 8192 + 4096;
        #pragma unroll
        for (int kc = 0; kc < 4; kc++) {
            uint32_t a[4], bf[4];
            ldsm_x4(a,  aBase + arow_l * 128 + (((2 * kc + akoff) ^ sx) << 4));
            ldsm_x4(bf, bBase + (nj * 16 + brow_l) * 128 + (((2 * kc + bkoff) ^ sx) << 4));
            mma_tf32(c, a, bf[nsel], bf[nsel + 1]);
        }
    }

    float* dst = d_attn_part + ((size_t)split * 128 + bh) * 1024;
    int row = wm * 16 + (lane >> 2);
    int col = wn * 8 + (lane & 3) * 2;
    dst[row * 32 + col]           = c[0];
    dst[row * 32 + col + 1]       = c[1];
    dst[(row + 8) * 32 + col]     = c[2];
    dst[(row + 8) * 32 + col + 1] = c[3];
}

// ------- attn finalize + softmax + wbT = (blockdiag attn @ proj_w)^T ---------
__global__ void __launch_bounds__(1024) attn_wb_kernel(const float* __restrict__ proj_w)
{
    int bh = blockIdx.x;
    int b = bh >> 3, h = bh & 7;
    int tid = threadIdx.x;
    int e = tid & 31, d = tid >> 5;

    __shared__ float sA[32][33];
    __shared__ float sW[32][256];

    float acc = 0.f;
    #pragma unroll
    for (int s = 0; s < NSPLIT; s++)
        acc += d_attn_part[((size_t)s * 128 + bh) * 1024 + d * 32 + e];

    float m = acc;
    #pragma unroll
    for (int o = 16; o; o >>= 1) m = fmaxf(m, __shfl_xor_sync(0xffffffffu, m, o));
    float ex = expf(acc - m);
    float sum = ex;
    #pragma unroll
    for (int o = 16; o; o >>= 1) sum += __shfl_xor_sync(0xffffffffu, sum, o);
    sA[d][e] = ex / sum;

    #pragma unroll
    for (int idx = tid; idx < 8192; idx += 1024)
        sW[idx >> 8][idx & 255] = proj_w[(h * 32 + (idx >> 8)) * 256 + (idx & 255)];
    __syncthreads();

    #pragma unroll
    for (int idx = tid; idx < 8192; idx += 1024) {
        int d2 = idx & 31, c = idx >> 5;
        float s = 0.f;
        #pragma unroll
        for (int ee = 0; ee < 32; ee++) s += sA[d2][ee] * sW[ee][c];
        d_wbT[(size_t)b * 65536 + c * 256 + h * 32 + d2] = s;
    }
}

// ---------------- launch ------------------------------------------------------
extern "C" void kernel_launch(void* const* d_in, const int* in_sizes, int n_in,
                              void* d_out, int out_size)
{
    const float* x        = (const float*)d_in[0];
    const float* dw_kernel= (const float*)d_in[1];
    const float* dw_bias  = (const float*)d_in[2];
    const float* ln_gamma = (const float*)d_in[3];
    const float* ln_beta  = (const float*)d_in[4];
    const float* qkv_w    = (const float*)d_in[5];
    const float* proj_w   = (const float*)d_in[6];
    const float* proj_b   = (const float*)d_in[7];
    const float* bn_gamma = (const float*)d_in[8];
    const float* bn_beta  = (const float*)d_in[9];
    const float* bn_mean  = (const float*)d_in[10];
    const float* bn_var   = (const float*)d_in[11];
    const float* fc1_w    = (const float*)d_in[12];
    const float* fc1_b    = (const float*)d_in[13];
    const float* fc2_w    = (const float*)d_in[14];
    const float* fc2_b    = (const float*)d_in[15];
    float* out = (float*)d_out;

    float *p_dwconv, *p_norm1, *p_v, *p_wbT, *p_merged, *p_h1;
    float *p_qkvT, *p_fc1T, *p_fc2T;
    cudaGetSymbolAddress((void**)&p_dwconv, d_dwconv);
    cudaGetSymbolAddress((void**)&p_norm1,  d_norm1);
    cudaGetSymbolAddress((void**)&p_v,      d_v);
    cudaGetSymbolAddress((void**)&p_wbT,    d_wbT);
    cudaGetSymbolAddress((void**)&p_merged, d_merged);
    cudaGetSymbolAddress((void**)&p_h1,     d_h1);
    cudaGetSymbolAddress((void**)&p_qkvT,   d_qkvT);
    cudaGetSymbolAddress((void**)&p_fc1T,   d_fc1T);
    cudaGetSymbolAddress((void**)&p_fc2T,   d_fc2T);

    cudaFuncSetAttribute(tgemm2<256, 4, false>,
                         cudaFuncAttributeMaxDynamicSharedMemorySize, TG_SMEM);
    cudaFuncSetAttribute(tgemm2<256, 1, true>,
                         cudaFuncAttributeMaxDynamicSharedMemorySize, TG_SMEM);
    cudaFuncSetAttribute(tgemm2<256, 2, false>,
                         cudaFuncAttributeMaxDynamicSharedMemorySize, TG_SMEM);
    cudaFuncSetAttribute(tgemm2<1024, 3, false>,
                         cudaFuncAttributeMaxDynamicSharedMemorySize, TG_SMEM);

    // 1) transpose weights
    transpose3_kernel<<<dim3(32, 32, 3), 256>>>(qkv_w, fc1_w, fc2_w);

    // 2) dwconv + cumsum + LN (warp-per-pixel, barrier-free)
    dwln_kernel<<<NTOK / 8, 256>>>(x, dw_kernel, dw_bias, ln_gamma, ln_beta);

    // 3) qkv GEMM in two half-M launches (keeps a tgemm2 in the ncu slot-4 window)
    tgemm2<256, 4, false><<<dim3(6, 98), 256, TG_SMEM>>>(
        p_norm1, 256, p_qkvT, p_v, 256, 0,
        nullptr, nullptr, nullptr, nullptr, nullptr, nullptr);
    tgemm2<256, 4, false><<<dim3(6, 98), 256, TG_SMEM>>>(
        p_norm1, 256, p_qkvT, p_v, 256, NTOK / 2,
        nullptr, nullptr, nullptr, nullptr, nullptr, nullptr);

    // 4) attn partials (tf32 mma, split-K x14)
    attn_split_kernel<<<dim3(BATCH * HEADS, NSPLIT), 256, AS_SMEM>>>();

    // 5) softmax + wbT
    attn_wb_kernel<<<BATCH * HEADS, 1024>>>(proj_w);

    // 6) merged = BN( v @ W_b + proj_b + dwconv )   [per-batch, 13 M-tiles]
    tgemm2<256, 1, true><<<dim3(2, BATCH * 13), 256, TG_SMEM>>>(
        p_v, 256, p_wbT, p_merged, 256, 0,
        proj_b, p_dwconv, bn_gamma, bn_beta, bn_mean, bn_var);

    // 7) h1 = gelu(merged @ fc1_w + fc1_b)
    tgemm2<256, 2, false><<<dim3(8, NTOK / 256), 256, TG_SMEM>>>(
        p_merged, 256, p_fc1T, p_h1, 1024, 0,
        fc1_b, nullptr, nullptr, nullptr, nullptr, nullptr);

    // 8) out = h1 @ fc2_w + fc2_b + x
    tgemm2<1024, 3, false><<<dim3(2, NTOK / 256), 256, TG_SMEM>>>(
        p_h1, 1024, p_fc2T, out, 256, 0,
        fc2_b, x, nullptr, nullptr, nullptr, nullptr);
}

// round 12
// speedup vs baseline: 1.2517x; 1.2517x over previous
#include <cuda_runtime.h>
#include <cuda_fp16.h>
#include <cstdint>
#include <math.h>

#define DIM     256
#define HEADS   8
#define HDIM    32
#define GW      64
#define HW      56
#define NPIX    3136            // 56*56
#define BATCH   16
#define NTOK    (BATCH * NPIX)  // 50176
#define HIDDEN  1024
#define LN_EPS  1e-6f
#define BN_EPS  1e-3f
#define L2_EPS  1e-12f
#define SCALE_Q 0.17677669529663689f  // 32^-0.5
#define NSPLIT  14                     // 3136 = 14 * 224

// ---------------- scratch (static device globals; no cudaMalloc) -------------
__device__ __align__(16) float  d_dwconv   [NTOK * DIM];
__device__ __align__(16) float  d_norm1    [NTOK * DIM];
__device__ __align__(16) float  d_qT       [BATCH * HEADS * HDIM * NPIX];
__device__ __align__(16) float  d_kT       [BATCH * HEADS * HDIM * NPIX];
__device__ __align__(16) float  d_v        [NTOK * DIM];
__device__ __align__(16) float  d_attn_part[NSPLIT * BATCH * HEADS * HDIM * HDIM];
__device__ __align__(16) float  d_wbT      [BATCH * DIM * DIM];
__device__ __align__(16) __half d_mergedh  [NTOK * DIM];
__device__ __align__(16) __half d_h1h      [NTOK * HIDDEN];
__device__ __align__(16) float  d_qkvT     [768 * 256];
__device__ __align__(16) __half d_fc1T     [1024 * 256];
__device__ __align__(16) __half d_fc2T     [256 * 1024];

// ---------------- PTX helpers -------------------------------------------------
__device__ __forceinline__ void cp_async16_s(uint32_t saddr, const void* gptr) {
    asm volatile("cp.async.cg.shared.global [%0], [%1], 16;\n" :: "r"(saddr), "l"(gptr));
}
__device__ __forceinline__ void cp_commit() { asm volatile("cp.async.commit_group;\n"); }

__device__ __forceinline__ void ldsm_x4(uint32_t r[4], uint32_t addr) {
    asm volatile("ldmatrix.sync.aligned.m8n8.x4.shared.b16 {%0,%1,%2,%3}, [%4];"
        : "=r"(r[0]), "=r"(r[1]), "=r"(r[2]), "=r"(r[3]) : "r"(addr));
}
__device__ __forceinline__ void mma_tf32(float c[4], const uint32_t a[4],
                                         uint32_t b0, uint32_t b1) {
    asm volatile(
        "mma.sync.aligned.m16n8k8.row.col.f32.tf32.tf32.f32 "
        "{%0,%1,%2,%3}, {%4,%5,%6,%7}, {%8,%9}, {%0,%1,%2,%3};"
        : "+f"(c[0]), "+f"(c[1]), "+f"(c[2]), "+f"(c[3])
        : "r"(a[0]), "r"(a[1]), "r"(a[2]), "r"(a[3]), "r"(b0), "r"(b1));
}
__device__ __forceinline__ void mma_f16(float c[4], const uint32_t a[4],
                                        uint32_t b0, uint32_t b1) {
    asm volatile(
        "mma.sync.aligned.m16n8k16.row.col.f32.f16.f16.f32 "
        "{%0,%1,%2,%3}, {%4,%5,%6,%7}, {%8,%9}, {%0,%1,%2,%3};"
        : "+f"(c[0]), "+f"(c[1]), "+f"(c[2]), "+f"(c[3])
        : "r"(a[0]), "r"(a[1]), "r"(a[2]), "r"(a[3]), "r"(b0), "r"(b1));
}

// ------- kernel 0: transpose weights; qkv -> fp32 [N,K], fc1/fc2 -> fp16 ------
__global__ void __launch_bounds__(256) transpose3_kernel(
    const float* __restrict__ qkv_w, const float* __restrict__ fc1_w,
    const float* __restrict__ fc2_w)
{
    const float* src; int R, C;
    if (blockIdx.z == 0)      { src = qkv_w; R = 256;  C = 768;  }
    else if (blockIdx.z == 1) { src = fc1_w; R = 256;  C = 1024; }
    else                      { src = fc2_w; R = 1024; C = 256;  }
    int x0 = blockIdx.x * 32, y0 = blockIdx.y * 32;
    if (x0 >= C || y0 >= R) return;

    __shared__ float t[32][33];
    int tx = threadIdx.x & 31, ty = threadIdx.x >> 5;
    #pragma unroll
    for (int i = ty; i < 32; i += 8)
        t[i][tx] = src[(size_t)(y0 + i) * C + x0 + tx];
    __syncthreads();
    #pragma unroll
    for (int i = ty; i < 32; i += 8) {
        if (blockIdx.z == 0)
            d_qkvT[(size_t)(x0 + i) * R + y0 + tx] = t[tx][i];
        else if (blockIdx.z == 1)
            d_fc1T[(size_t)(x0 + i) * R + y0 + tx] = __float2half(t[tx][i]);
        else
            d_fc2T[(size_t)(x0 + i) * R + y0 + tx] = __float2half(t[tx][i]);
    }
}

// ---- kernel 1: dwconv3x3 + group cumsum + LayerNorm, warp-per-pixel ---------
__global__ void __launch_bounds__(256) dwln_kernel(
    const float* __restrict__ x, const float* __restrict__ dwk,
    const float* __restrict__ dwb, const float* __restrict__ g,
    const float* __restrict__ be)
{
    const int lane = threadIdx.x & 31;
    const int wrp  = threadIdx.x >> 5;
    const int pix  = blockIdx.x * 8 + wrp;
    const int b  = pix / NPIX;
    const int p  = pix - b * NPIX;
    const int hh = p / HW, ww = p - hh * HW;
    const int c  = lane * 8;

    float val[8];
    if (lane < 8) {
        float4 a0 = *(const float4*)&x[(size_t)pix * DIM + c];
        float4 a1 = *(const float4*)&x[(size_t)pix * DIM + c + 4];
        val[0]=a0.x; val[1]=a0.y; val[2]=a0.z; val[3]=a0.w;
        val[4]=a1.x; val[5]=a1.y; val[6]=a1.z; val[7]=a1.w;
    } else {
        const int cc = c - GW;
        float4 b0 = *(const float4*)&dwb[cc];
        float4 b1 = *(const float4*)&dwb[cc + 4];
        val[0]=b0.x; val[1]=b0.y; val[2]=b0.z; val[3]=b0.w;
        val[4]=b1.x; val[5]=b1.y; val[6]=b1.z; val[7]=b1.w;
        #pragma unroll
        for (int ky = 0; ky < 3; ky++) {
            int hy = hh + ky - 1;
            if ((unsigned)hy < (unsigned)HW) {
                #pragma unroll
                for (int kx = 0; kx < 3; kx++) {
                    int wx = ww + kx - 1;
                    if ((unsigned)wx < (unsigned)HW) {
                        const float* xp = &x[((size_t)(b * HW + hy) * HW + wx) * DIM + c];
                        const float* wp = &dwk[(ky * 3 + kx) * 192 + cc];
                        float4 x0 = *(const float4*)xp, x1 = *(const float4*)(xp + 4);
                        float4 w0 = *(const float4*)wp, w1 = *(const float4*)(wp + 4);
                        val[0] += x0.x * w0.x; val[1] += x0.y * w0.y;
                        val[2] += x0.z * w0.z; val[3] += x0.w * w0.w;
                        val[4] += x1.x * w1.x; val[5] += x1.y * w1.y;
                        val[6] += x1.z * w1.z; val[7] += x1.w * w1.w;
                    }
                }
            }
        }
    }

    {
        const int s0 = 8 + (lane & 7);
        const int gi = (lane >> 3) - 1;
        #pragma unroll
        for (int i = 0; i < 8; i++) {
            float k0 = __shfl_sync(0xffffffffu, val[i], s0);
            float k1 = __shfl_sync(0xffffffffu, val[i], s0 + 8);
            float k2 = __shfl_sync(0xffffffffu, val[i], s0 + 16);
            if (lane >= 8) {
                float s = k0;
                if (gi >= 1) s += k1;
                if (gi >= 2) s += k2;
                val[i] = s;
            }
        }
    }

    float sum = 0.f;
    #pragma unroll
    for (int i = 0; i < 8; i++) sum += val[i];
    #pragma unroll
    for (int o = 16; o; o >>= 1) sum += __shfl_xor_sync(0xffffffffu, sum, o);
    float mean = sum * (1.0f / 256.0f);

    float ss = 0.f;
    #pragma unroll
    for (int i = 0; i < 8; i++) { float d = val[i] - mean; ss += d * d; }
    #pragma unroll
    for (int o = 16; o; o >>= 1) ss += __shfl_xor_sync(0xffffffffu, ss, o);
    float rstd = rsqrtf(ss * (1.0f / 256.0f) + LN_EPS);

    float4 g0 = *(const float4*)&g[c],  g1 = *(const float4*)&g[c + 4];
    float4 e0 = *(const float4*)&be[c], e1 = *(const float4*)&be[c + 4];
    *(float4*)&d_dwconv[(size_t)pix * DIM + c]     = make_float4(val[0], val[1], val[2], val[3]);
    *(float4*)&d_dwconv[(size_t)pix * DIM + c + 4] = make_float4(val[4], val[5], val[6], val[7]);
    float4 n0 = make_float4((val[0]-mean)*rstd*g0.x+e0.x, (val[1]-mean)*rstd*g0.y+e0.y,
                            (val[2]-mean)*rstd*g0.z+e0.z, (val[3]-mean)*rstd*g0.w+e0.w);
    float4 n1 = make_float4((val[4]-mean)*rstd*g1.x+e1.x, (val[5]-mean)*rstd*g1.y+e1.y,
                            (val[6]-mean)*rstd*g1.z+e1.z, (val[7]-mean)*rstd*g1.w+e1.w);
    *(float4*)&d_norm1[(size_t)pix * DIM + c]     = n0;
    *(float4*)&d_norm1[(size_t)pix * DIM + c + 4] = n1;
}

// ------- tf32 GEMM (R10 config): BM=128 BN=128, 2 CTA/SM, single barrier -----
// MODE 1: BN( +bias +add1 ) -> fp16 merged    MODE 4: qkv (l2norm, qT/kT/v)
#define TG_BOFF  49152
#define TG_SMEM  98304

template<int KDIM, int MODE, bool PERBATCH>
__global__ void __launch_bounds__(256, 2)
tgemm2(const float* __restrict__ A, int lda,
       const float* __restrict__ Bt,
       float* __restrict__ C, int ldc, int m_off,
       const float* __restrict__ bias, const float* __restrict__ add1,
       const float* __restrict__ bn_g, const float* __restrict__ bn_b,
       const float* __restrict__ bn_m, const float* __restrict__ bn_v)
{
    extern __shared__ char smem[];
    const uint32_t sb = (uint32_t)__cvta_generic_to_shared(smem);
    const int tid  = threadIdx.x;
    const int lane = tid & 31;
    const int w    = tid >> 5;
    const int wm   = w >> 2;
    const int wn   = w & 3;

    int m0, mrows;
    if (PERBATCH) {
        int batch = blockIdx.y / 25;
        int bt    = blockIdx.y % 25;
        m0 = batch * NPIX + bt * 128;
        mrows = min(128, NPIX - bt * 128);
    } else {
        m0 = m_off + blockIdx.y * 128; mrows = 128;
    }
    const int n0 = blockIdx.x * 128;
    const float* Bp = PERBATCH ? (Bt + (size_t)(blockIdx.y / 25) * 65536) : Bt;

    float acc[4][4][4];
    #pragma unroll
    for (int mi = 0; mi < 4; mi++)
        #pragma unroll
        for (int ni = 0; ni < 4; ni++)
            #pragma unroll
            for (int q = 0; q < 4; q++) acc[mi][ni][q] = 0.f;

    auto load_stage = [&](int st) {
        int slot = st % 3;
        int k0 = st * 32;
        #pragma unroll
        for (int i = 0; i < 4; i++) {
            int lin = tid + 256 * i;
            int r = lin >> 3, ch = lin & 7;
            int rg = m0 + (r < mrows ? r : mrows - 1);
            cp_async16_s(sb + slot * 16384 + r * 128 + ((ch ^ (r & 7)) << 4),
                         A + (size_t)rg * lda + k0 + ch * 4);
        }
        #pragma unroll
        for (int i = 0; i < 4; i++) {
            int lin = tid + 256 * i;
            int r = lin >> 3, ch = lin & 7;
            cp_async16_s(sb + TG_BOFF + slot * 16384 + r * 128 + ((ch ^ (r & 7)) << 4),
                         Bp + (size_t)(n0 + r) * KDIM + k0 + ch * 4);
        }
        cp_commit();
    };

    const int KT = KDIM / 32;
    load_stage(0); load_stage(1);

    const int arow_l = (lane & 7) + ((lane >> 3) & 1) * 8;
    const int akoff  = lane >> 4;
    const int brow_l = (lane & 7) + (lane >> 4) * 8;
    const int bkoff  = (lane >> 3) & 1;
    const int sx     = lane & 7;

    for (int s = 0; s < KT; s++) {
        int slot = s % 3;
        if (s < KT - 1) asm volatile("cp.async.wait_group 1;\n" ::: "memory");
        else            asm volatile("cp.async.wait_group 0;\n" ::: "memory");
        __syncthreads();
        if (s + 2 < KT) load_stage(s + 2);

        uint32_t aBase = sb + slot * 16384 + (wm * 64) * 128;
        uint32_t bBase = sb + TG_BOFF + slot * 16384 + (wn * 32) * 128;

        #pragma unroll
        for (int kc = 0; kc < 4; kc++) {
            uint32_t a[4][4];
            #pragma unroll
            for (int mi = 0; mi < 4; mi++)
                ldsm_x4(a[mi], aBase + (mi * 16 + arow_l) * 128
                               + (((2 * kc + akoff) ^ sx) << 4));
            uint32_t bf[2][4];
            #pragma unroll
            for (int nj = 0; nj < 2; nj++)
                ldsm_x4(bf[nj], bBase + (nj * 16 + brow_l) * 128
                                + (((2 * kc + bkoff) ^ sx) << 4));
            #pragma unroll
            for (int mi = 0; mi < 4; mi++)
                #pragma unroll
                for (int ni = 0; ni < 4; ni++)
                    mma_tf32(acc[mi][ni], a[mi],
                             bf[ni >> 1][(ni & 1) * 2], bf[ni >> 1][(ni & 1) * 2 + 1]);
        }
    }

    // ---- MODE 4 q/k path ----
    if (MODE == 4 && n0 < 512) {
        float* sT = (float*)smem;             // [col 128][row 128], stride 132
        __syncthreads();
        #pragma unroll
        for (int mi = 0; mi < 4; mi++) {
            #pragma unroll
            for (int h = 0; h < 2; h++) {
                float ss = 0.f;
                #pragma unroll
                for (int ni = 0; ni < 4; ni++) {
                    float v0 = acc[mi][ni][2 * h], v1 = acc[mi][ni][2 * h + 1];
                    ss += v0 * v0 + v1 * v1;
                }
                ss += __shfl_xor_sync(0xffffffffu, ss, 1);
                ss += __shfl_xor_sync(0xffffffffu, ss, 2);
                float sc = rsqrtf(fmaxf(ss, L2_EPS));
                if (n0 < 256) sc *= SCALE_Q;

                int rowl = wm * 64 + mi * 16 + (lane >> 2) + h * 8;
                #pragma unroll
                for (int ni = 0; ni < 4; ni++) {
                    int dl = wn * 32 + ni * 8 + (lane & 3) * 2;
                    sT[dl * 132 + rowl]       = acc[mi][ni][2 * h] * sc;
                    sT[(dl + 1) * 132 + rowl] = acc[mi][ni][2 * h + 1] * sc;
                }
            }
        }
        __syncthreads();
        float* dstT = (n0 < 256) ? d_qT : d_kT;
        #pragma unroll
        for (int i = 0; i < 16; i++) {
            int idx = tid + i * 256;
            int cl  = idx >> 5;
            int row = (idx & 31) * 4;
            int grow = m0 + row;
            int bb = grow / NPIX;
            int n  = grow - bb * NPIX;
            int gcol = n0 + cl;
            int head = (gcol & 255) >> 5;
            int d    = gcol & 31;
            float4 v4 = *(float4*)&sT[cl * 132 + row];
            *(float4*)&dstT[((size_t)(bb * 8 + head) * 32 + d) * NPIX + n] = v4;
        }
        return;
    }

    // ---- epilogue ----
    #pragma unroll
    for (int mi = 0; mi < 4; mi++) {
        #pragma unroll
        for (int h = 0; h < 2; h++) {
            int lr = wm * 64 + mi * 16 + (lane >> 2) + h * 8;
            if (PERBATCH && lr >= mrows) continue;
            size_t grow = (size_t)(m0 + lr);

            #pragma unroll
            for (int ni = 0; ni < 4; ni++) {
                float v0 = acc[mi][ni][2 * h], v1 = acc[mi][ni][2 * h + 1];
                if (MODE == 4) {
                    int gc = (n0 - 512) + wn * 32 + ni * 8 + (lane & 3) * 2;
                    *(float2*)&C[grow * ldc + gc] = make_float2(v0, v1);
                    continue;
                }
                int gc = n0 + wn * 32 + ni * 8 + (lane & 3) * 2;
                if (MODE == 1) {
                    float2 ad = *(const float2*)&add1[grow * 256 + gc];
                    v0 += bias[gc]     + ad.x;
                    v1 += bias[gc + 1] + ad.y;
                    v0 = (v0 - bn_m[gc    ]) * rsqrtf(bn_v[gc    ] + BN_EPS) * bn_g[gc    ] + bn_b[gc    ];
                    v1 = (v1 - bn_m[gc + 1]) * rsqrtf(bn_v[gc + 1] + BN_EPS) * bn_g[gc + 1] + bn_b[gc + 1];
                    *(__half2*)((__half*)C + grow * ldc + gc) = __floats2half2_rn(v0, v1);
                    continue;
                }
                *(float2*)&C[grow * ldc + gc] = make_float2(v0, v1);
            }
        }
    }
}

// -------- fp16 GEMM (fc1/fc2): BM=128 BN=128 BK=32, 4-stage single-barrier ----
// MODE 2: gelu(+bias) -> half    MODE 3: +bias +add1 -> float
#define HG_STAGE 10240
#define HG_B_OFF 40960
#define HG_SMEM  81920

template<int KDIM, int MODE>
__global__ void __launch_bounds__(256, 2)
hgemm(const __half* __restrict__ A,
      const __half* __restrict__ Bt,
      void* __restrict__ Cv, int ldc,
      const float* __restrict__ bias, const float* __restrict__ add1)
{
    extern __shared__ char smem[];
    const uint32_t sb = (uint32_t)__cvta_generic_to_shared(smem);
    const int tid  = threadIdx.x;
    const int lane = tid & 31;
    const int w    = tid >> 5;
    const int wm   = w >> 2;
    const int wn   = w & 3;

    const int m0 = blockIdx.y * 128;
    const int n0 = blockIdx.x * 128;

    float acc[4][4][4];
    #pragma unroll
    for (int mi = 0; mi < 4; mi++)
        #pragma unroll
        for (int ni = 0; ni < 4; ni++)
            #pragma unroll
            for (int q = 0; q < 4; q++) acc[mi][ni][q] = 0.f;

    auto load_stage = [&](int st) {
        int slot = st & 3;
        int k0 = st * 32;
        int r  = tid >> 1;
        int ch = (tid & 1);
        {
            const __half* gp = A + (size_t)(m0 + r) * KDIM + k0 + ch * 16;
            uint32_t dst = sb + slot * HG_STAGE + r * 80 + ch * 32;
            cp_async16_s(dst, gp);
            cp_async16_s(dst + 16, gp + 8);
        }
        {
            const __half* gp = Bt + (size_t)(n0 + r) * KDIM + k0 + ch * 16;
            uint32_t dst = sb + HG_B_OFF + slot * HG_STAGE + r * 80 + ch * 32;
            cp_async16_s(dst, gp);
            cp_async16_s(dst + 16, gp + 8);
        }
        cp_commit();
    };

    const int KT = KDIM / 32;
    load_stage(0); load_stage(1); load_stage(2);

    for (int s = 0; s < KT; s++) {
        int slot = s & 3;
        if (s < KT - 2)       asm volatile("cp.async.wait_group 2;\n" ::: "memory");
        else if (s == KT - 2) asm volatile("cp.async.wait_group 1;\n" ::: "memory");
        else                  asm volatile("cp.async.wait_group 0;\n" ::: "memory");
        __syncthreads();
        // barrier proves slot (s-1)&3 fully consumed -> safe to refill as s+3
        if (s + 3 < KT) load_stage(s + 3);

        uint32_t aBase = sb + slot * HG_STAGE + (wm * 64) * 80;
        uint32_t bBase = sb + HG_B_OFF + slot * HG_STAGE + (wn * 32) * 80;
        #pragma unroll
        for (int ks = 0; ks < 2; ks++) {
            const int kc = ks * 2;
            uint32_t a[4][4];
            #pragma unroll
            for (int mi = 0; mi < 4; mi++) {
                uint32_t addr = aBase + (mi * 16 + (lane & 15)) * 80
                              + (kc + (lane >> 4)) * 16;
                ldsm_x4(a[mi], addr);
            }
            uint32_t bf[2][4];
            #pragma unroll
            for (int nj = 0; nj < 2; nj++) {
                uint32_t addr = bBase + (nj * 16 + ((lane >> 4) << 3) + (lane & 7)) * 80
                              + (kc + ((lane >> 3) & 1)) * 16;
                ldsm_x4(bf[nj], addr);
            }
            #pragma unroll
            for (int mi = 0; mi < 4; mi++)
                #pragma unroll
                for (int ni = 0; ni < 4; ni++)
                    mma_f16(acc[mi][ni], a[mi],
                            bf[ni >> 1][(ni & 1) * 2], bf[ni >> 1][(ni & 1) * 2 + 1]);
        }
    }

    #pragma unroll
    for (int mi = 0; mi < 4; mi++) {
        #pragma unroll
        for (int h = 0; h < 2; h++) {
            int lr = wm * 64 + mi * 16 + (lane >> 2) + h * 8;
            size_t grow = (size_t)(m0 + lr);
            #pragma unroll
            for (int ni = 0; ni < 4; ni++) {
                int gc = n0 + wn * 32 + ni * 8 + (lane & 3) * 2;
                float v0 = acc[mi][ni][2 * h], v1 = acc[mi][ni][2 * h + 1];
                if (MODE == 2) {
                    v0 += bias[gc];   v1 += bias[gc + 1];
                    v0 = 0.5f * v0 * (1.0f + erff(v0 * 0.70710678118654752f));
                    v1 = 0.5f * v1 * (1.0f + erff(v1 * 0.70710678118654752f));
                    *(__half2*)((__half*)Cv + grow * ldc + gc) = __floats2half2_rn(v0, v1);
                } else {
                    float2 ad = *(const float2*)&add1[grow * 256 + gc];
                    v0 += bias[gc]     + ad.x;
                    v1 += bias[gc + 1] + ad.y;
                    *(float2*)&((float*)Cv)[grow * ldc + gc] = make_float2(v0, v1);
                }
            }
        }
    }
}

// ------- attn split-K: per (b,h,split) partial 32x32 q^T k via tf32 mma ------
#define AS_SMEM 24576

__global__ void __launch_bounds__(256) attn_split_kernel()
{
    extern __shared__ char smem[];
    const uint32_t sb = (uint32_t)__cvta_generic_to_shared(smem);
    const int bh = blockIdx.x;
    const int split = blockIdx.y;
    const int tid = threadIdx.x, lane = tid & 31, w = tid >> 5;
    const int wm = w >> 2, wn = w & 3;

    const float* qT = d_qT + (size_t)bh * 32 * NPIX + split * 224;
    const float* kT = d_kT + (size_t)bh * 32 * NPIX + split * 224;

    float c[4] = {0.f, 0.f, 0.f, 0.f};

    auto load_stage = [&](int st) {
        int slot = st % 3;
        int k0 = st * 32;
        int r = tid >> 3, ch = tid & 7;
        uint32_t dst = sb + slot * 8192 + r * 128 + ((ch ^ (r & 7)) << 4);
        cp_async16_s(dst,        qT + (size_t)r * NPIX + k0 + ch * 4);
        cp_async16_s(dst + 4096, kT + (size_t)r * NPIX + k0 + ch * 4);
        cp_commit();
    };

    const int KT = 7;
    load_stage(0); load_stage(1);

    const int arow_l = (lane & 7) + ((lane >> 3) & 1) * 8;
    const int akoff  = lane >> 4;
    const int brow_l = (lane & 7) + (lane >> 4) * 8;
    const int bkoff  = (lane >> 3) & 1;
    const int sx     = lane & 7;
    const int nj     = wn >> 1;
    const int nsel   = (wn & 1) * 2;

    for (int s = 0; s < KT; s++) {
        int slot = s % 3;
        if (s < KT - 1) asm volatile("cp.async.wait_group 1;\n" ::: "memory");
        else            asm volatile("cp.async.wait_group 0;\n" ::: "memory");
        __syncthreads();
        if (s + 2 < KT) load_stage(s + 2);

        uint32_t aBase = sb + slot * 8192 + (wm * 16) * 128;
        uint32_t bBase = sb + slot * 8192 + 4096;
        #pragma unroll
        for (int kc = 0; kc < 4; kc++) {
            uint32_t a[4], bf[4];
            ldsm_x4(a,  aBase + arow_l * 128 + (((2 * kc + akoff) ^ sx) << 4));
            ldsm_x4(bf, bBase + (nj * 16 + brow_l) * 128 + (((2 * kc + bkoff) ^ sx) << 4));
            mma_tf32(c, a, bf[nsel], bf[nsel + 1]);
        }
    }

    float* dst = d_attn_part + ((size_t)split * 128 + bh) * 1024;
    int row = wm * 16 + (lane >> 2);
    int col = wn * 8 + (lane & 3) * 2;
    dst[row * 32 + col]           = c[0];
    dst[row * 32 + col + 1]       = c[1];
    dst[(row + 8) * 32 + col]     = c[2];
    dst[(row + 8) * 32 + col + 1] = c[3];
}

// ------- attn finalize + softmax + wbT = (blockdiag attn @ proj_w)^T ---------
__global__ void __launch_bounds__(1024) attn_wb_kernel(const float* __restrict__ proj_w)
{
    int bh = blockIdx.x;
    int b = bh >> 3, h = bh & 7;
    int tid = threadIdx.x;
    int e = tid & 31, d = tid >> 5;

    __shared__ float sA[32][33];
    __shared__ float sW[32][256];

    float acc = 0.f;
    #pragma unroll
    for (int s = 0; s < NSPLIT; s++)
        acc += d_attn_part[((size_t)s * 128 + bh) * 1024 + d * 32 + e];

    float m = acc;
    #pragma unroll
    for (int o = 16; o; o >>= 1) m = fmaxf(m, __shfl_xor_sync(0xffffffffu, m, o));
    float ex = expf(acc - m);
    float sum = ex;
    #pragma unroll
    for (int o = 16; o; o >>= 1) sum += __shfl_xor_sync(0xffffffffu, sum, o);
    sA[d][e] = ex / sum;

    #pragma unroll
    for (int idx = tid; idx < 8192; idx += 1024)
        sW[idx >> 8][idx & 255] = proj_w[(h * 32 + (idx >> 8)) * 256 + (idx & 255)];
    __syncthreads();

    #pragma unroll
    for (int idx = tid; idx < 8192; idx += 1024) {
        int d2 = idx & 31, c = idx >> 5;
        float s = 0.f;
        #pragma unroll
        for (int ee = 0; ee < 32; ee++) s += sA[d2][ee] * sW[ee][c];
        d_wbT[(size_t)b * 65536 + c * 256 + h * 32 + d2] = s;
    }
}

// ---------------- launch ------------------------------------------------------
extern "C" void kernel_launch(void* const* d_in, const int* in_sizes, int n_in,
                              void* d_out, int out_size)
{
    const float* x        = (const float*)d_in[0];
    const float* dw_kernel= (const float*)d_in[1];
    const float* dw_bias  = (const float*)d_in[2];
    const float* ln_gamma = (const float*)d_in[3];
    const float* ln_beta  = (const float*)d_in[4];
    const float* qkv_w    = (const float*)d_in[5];
    const float* proj_w   = (const float*)d_in[6];
    const float* proj_b   = (const float*)d_in[7];
    const float* bn_gamma = (const float*)d_in[8];
    const float* bn_beta  = (const float*)d_in[9];
    const float* bn_mean  = (const float*)d_in[10];
    const float* bn_var   = (const float*)d_in[11];
    const float* fc1_w    = (const float*)d_in[12];
    const float* fc1_b    = (const float*)d_in[13];
    const float* fc2_w    = (const float*)d_in[14];
    const float* fc2_b    = (const float*)d_in[15];
    float* out = (float*)d_out;

    float  *p_dwconv, *p_norm1, *p_v, *p_wbT, *p_qkvT;
    __half *p_mergedh, *p_h1h, *p_fc1T, *p_fc2T;
    cudaGetSymbolAddress((void**)&p_dwconv,  d_dwconv);
    cudaGetSymbolAddress((void**)&p_norm1,   d_norm1);
    cudaGetSymbolAddress((void**)&p_v,       d_v);
    cudaGetSymbolAddress((void**)&p_wbT,     d_wbT);
    cudaGetSymbolAddress((void**)&p_mergedh, d_mergedh);
    cudaGetSymbolAddress((void**)&p_h1h,     d_h1h);
    cudaGetSymbolAddress((void**)&p_qkvT,    d_qkvT);
    cudaGetSymbolAddress((void**)&p_fc1T,    d_fc1T);
    cudaGetSymbolAddress((void**)&p_fc2T,    d_fc2T);

    cudaFuncSetAttribute(tgemm2<256, 4, false>,
                         cudaFuncAttributeMaxDynamicSharedMemorySize, TG_SMEM);
    cudaFuncSetAttribute(tgemm2<256, 1, true>,
                         cudaFuncAttributeMaxDynamicSharedMemorySize, TG_SMEM);
    cudaFuncSetAttribute(hgemm<256, 2>,
                         cudaFuncAttributeMaxDynamicSharedMemorySize, HG_SMEM);
    cudaFuncSetAttribute(hgemm<1024, 3>,
                         cudaFuncAttributeMaxDynamicSharedMemorySize, HG_SMEM);

    // 1) transpose weights (qkv fp32; fc1/fc2 fp16)
    transpose3_kernel<<<dim3(32, 32, 3), 256>>>(qkv_w, fc1_w, fc2_w);

    // 2) dwconv + cumsum + LN
    dwln_kernel<<<NTOK / 8, 256>>>(x, dw_kernel, dw_bias, ln_gamma, ln_beta);

    // 3) qkv GEMM (tf32), two half-M launches (slot-4 ncu A/B vs R10)
    tgemm2<256, 4, false><<<dim3(6, 196), 256, TG_SMEM>>>(
        p_norm1, 256, p_qkvT, p_v, 256, 0,
        nullptr, nullptr, nullptr, nullptr, nullptr, nullptr);
    tgemm2<256, 4, false><<<dim3(6, 196), 256, TG_SMEM>>>(
        p_norm1, 256, p_qkvT, p_v, 256, NTOK / 2,
        nullptr, nullptr, nullptr, nullptr, nullptr, nullptr);

    // 4) attn partials (tf32 mma, split-K x14)
    attn_split_kernel<<<dim3(BATCH * HEADS, NSPLIT), 256, AS_SMEM>>>();

    // 5) softmax + wbT
    attn_wb_kernel<<<BATCH * HEADS, 1024>>>(proj_w);

    // 6) merged = BN( v @ W_b + proj_b + dwconv ) -> fp16   (tf32 GEMM)
    tgemm2<256, 1, true><<<dim3(2, BATCH * 25), 256, TG_SMEM>>>(
        p_v, 256, p_wbT, (float*)p_mergedh, 256, 0,
        proj_b, p_dwconv, bn_gamma, bn_beta, bn_mean, bn_var);

    // 7) h1 = gelu(merged @ fc1_w + fc1_b) -> fp16          (fp16 GEMM)
    hgemm<256, 2><<<dim3(8, NTOK / 128), 256, HG_SMEM>>>(
        p_mergedh, p_fc1T, p_h1h, 1024, fc1_b, nullptr);

    // 8) out = h1 @ fc2_w + fc2_b + x -> fp32               (fp16 GEMM)
    hgemm<1024, 3><<<dim3(2, NTOK / 128), 256, HG_SMEM>>>(
        p_h1h, p_fc2T, out, 256, fc2_b, x);
}

// round 13
// speedup vs baseline: 1.3435x; 1.0733x over previous
#include <cuda_runtime.h>
#include <cuda_fp16.h>
#include <cstdint>
#include <math.h>

#define DIM     256
#define HEADS   8
#define HDIM    32
#define GW      64
#define HW      56
#define NPIX    3136            // 56*56
#define BATCH   16
#define NTOK    (BATCH * NPIX)  // 50176
#define HIDDEN  1024
#define LN_EPS  1e-6f
#define BN_EPS  1e-3f
#define L2_EPS  1e-12f
#define SCALE_Q 0.17677669529663689f  // 32^-0.5
#define NSPLIT  14                     // 3136 = 14 * 224

// ---------------- scratch (static device globals; no cudaMalloc) -------------
__device__ __align__(16) float  d_dwconv   [NTOK * DIM];
__device__ __align__(16) __half d_norm1h   [NTOK * DIM];
__device__ __align__(16) float  d_qT       [BATCH * HEADS * HDIM * NPIX];
__device__ __align__(16) float  d_kT       [BATCH * HEADS * HDIM * NPIX];
__device__ __align__(16) float  d_v        [NTOK * DIM];
__device__ __align__(16) float  d_attn_part[NSPLIT * BATCH * HEADS * HDIM * HDIM];
__device__ __align__(16) float  d_wbT      [BATCH * DIM * DIM];
__device__ __align__(16) __half d_mergedh  [NTOK * DIM];
__device__ __align__(16) __half d_h1h      [NTOK * HIDDEN];
__device__ __align__(16) __half d_qkvTh    [768 * 256];
__device__ __align__(16) __half d_fc1T     [1024 * 256];
__device__ __align__(16) __half d_fc2T     [256 * 1024];

// ---------------- PTX helpers -------------------------------------------------
__device__ __forceinline__ void cp_async16_s(uint32_t saddr, const void* gptr) {
    asm volatile("cp.async.cg.shared.global [%0], [%1], 16;\n" :: "r"(saddr), "l"(gptr));
}
__device__ __forceinline__ void cp_commit() { asm volatile("cp.async.commit_group;\n"); }

__device__ __forceinline__ void ldsm_x4(uint32_t r[4], uint32_t addr) {
    asm volatile("ldmatrix.sync.aligned.m8n8.x4.shared.b16 {%0,%1,%2,%3}, [%4];"
        : "=r"(r[0]), "=r"(r[1]), "=r"(r[2]), "=r"(r[3]) : "r"(addr));
}
__device__ __forceinline__ void mma_tf32(float c[4], const uint32_t a[4],
                                         uint32_t b0, uint32_t b1) {
    asm volatile(
        "mma.sync.aligned.m16n8k8.row.col.f32.tf32.tf32.f32 "
        "{%0,%1,%2,%3}, {%4,%5,%6,%7}, {%8,%9}, {%0,%1,%2,%3};"
        : "+f"(c[0]), "+f"(c[1]), "+f"(c[2]), "+f"(c[3])
        : "r"(a[0]), "r"(a[1]), "r"(a[2]), "r"(a[3]), "r"(b0), "r"(b1));
}
__device__ __forceinline__ void mma_f16(float c[4], const uint32_t a[4],
                                        uint32_t b0, uint32_t b1) {
    asm volatile(
        "mma.sync.aligned.m16n8k16.row.col.f32.f16.f16.f32 "
        "{%0,%1,%2,%3}, {%4,%5,%6,%7}, {%8,%9}, {%0,%1,%2,%3};"
        : "+f"(c[0]), "+f"(c[1]), "+f"(c[2]), "+f"(c[3])
        : "r"(a[0]), "r"(a[1]), "r"(a[2]), "r"(a[3]), "r"(b0), "r"(b1));
}

// ------- kernel 0: transpose weights -> fp16 [N, K] ---------------------------
__global__ void __launch_bounds__(256) transpose3_kernel(
    const float* __restrict__ qkv_w, const float* __restrict__ fc1_w,
    const float* __restrict__ fc2_w)
{
    const float* src; int R, C;
    if (blockIdx.z == 0)      { src = qkv_w; R = 256;  C = 768;  }
    else if (blockIdx.z == 1) { src = fc1_w; R = 256;  C = 1024; }
    else                      { src = fc2_w; R = 1024; C = 256;  }
    int x0 = blockIdx.x * 32, y0 = blockIdx.y * 32;
    if (x0 >= C || y0 >= R) return;

    __shared__ float t[32][33];
    int tx = threadIdx.x & 31, ty = threadIdx.x >> 5;
    #pragma unroll
    for (int i = ty; i < 32; i += 8)
        t[i][tx] = src[(size_t)(y0 + i) * C + x0 + tx];
    __syncthreads();
    #pragma unroll
    for (int i = ty; i < 32; i += 8) {
        if (blockIdx.z == 0)
            d_qkvTh[(size_t)(x0 + i) * R + y0 + tx] = __float2half(t[tx][i]);
        else if (blockIdx.z == 1)
            d_fc1T[(size_t)(x0 + i) * R + y0 + tx] = __float2half(t[tx][i]);
        else
            d_fc2T[(size_t)(x0 + i) * R + y0 + tx] = __float2half(t[tx][i]);
    }
}

// ---- kernel 1: dwconv3x3 + group cumsum + LayerNorm, warp-per-pixel ---------
// dwconv kept fp32 (proj epilogue add), norm1 stored fp16 (qkv GEMM A-operand)
__global__ void __launch_bounds__(256) dwln_kernel(
    const float* __restrict__ x, const float* __restrict__ dwk,
    const float* __restrict__ dwb, const float* __restrict__ g,
    const float* __restrict__ be)
{
    const int lane = threadIdx.x & 31;
    const int wrp  = threadIdx.x >> 5;
    const int pix  = blockIdx.x * 8 + wrp;
    const int b  = pix / NPIX;
    const int p  = pix - b * NPIX;
    const int hh = p / HW, ww = p - hh * HW;
    const int c  = lane * 8;

    float val[8];
    if (lane < 8) {
        float4 a0 = *(const float4*)&x[(size_t)pix * DIM + c];
        float4 a1 = *(const float4*)&x[(size_t)pix * DIM + c + 4];
        val[0]=a0.x; val[1]=a0.y; val[2]=a0.z; val[3]=a0.w;
        val[4]=a1.x; val[5]=a1.y; val[6]=a1.z; val[7]=a1.w;
    } else {
        const int cc = c - GW;
        float4 b0 = *(const float4*)&dwb[cc];
        float4 b1 = *(const float4*)&dwb[cc + 4];
        val[0]=b0.x; val[1]=b0.y; val[2]=b0.z; val[3]=b0.w;
        val[4]=b1.x; val[5]=b1.y; val[6]=b1.z; val[7]=b1.w;
        #pragma unroll
        for (int ky = 0; ky < 3; ky++) {
            int hy = hh + ky - 1;
            if ((unsigned)hy < (unsigned)HW) {
                #pragma unroll
                for (int kx = 0; kx < 3; kx++) {
                    int wx = ww + kx - 1;
                    if ((unsigned)wx < (unsigned)HW) {
                        const float* xp = &x[((size_t)(b * HW + hy) * HW + wx) * DIM + c];
                        const float* wp = &dwk[(ky * 3 + kx) * 192 + cc];
                        float4 x0 = *(const float4*)xp, x1 = *(const float4*)(xp + 4);
                        float4 w0 = *(const float4*)wp, w1 = *(const float4*)(wp + 4);
                        val[0] += x0.x * w0.x; val[1] += x0.y * w0.y;
                        val[2] += x0.z * w0.z; val[3] += x0.w * w0.w;
                        val[4] += x1.x * w1.x; val[5] += x1.y * w1.y;
                        val[6] += x1.z * w1.z; val[7] += x1.w * w1.w;
                    }
                }
            }
        }
    }

    {
        const int s0 = 8 + (lane & 7);
        const int gi = (lane >> 3) - 1;
        #pragma unroll
        for (int i = 0; i < 8; i++) {
            float k0 = __shfl_sync(0xffffffffu, val[i], s0);
            float k1 = __shfl_sync(0xffffffffu, val[i], s0 + 8);
            float k2 = __shfl_sync(0xffffffffu, val[i], s0 + 16);
            if (lane >= 8) {
                float s = k0;
                if (gi >= 1) s += k1;
                if (gi >= 2) s += k2;
                val[i] = s;
            }
        }
    }

    float sum = 0.f;
    #pragma unroll
    for (int i = 0; i < 8; i++) sum += val[i];
    #pragma unroll
    for (int o = 16; o; o >>= 1) sum += __shfl_xor_sync(0xffffffffu, sum, o);
    float mean = sum * (1.0f / 256.0f);

    float ss = 0.f;
    #pragma unroll
    for (int i = 0; i < 8; i++) { float d = val[i] - mean; ss += d * d; }
    #pragma unroll
    for (int o = 16; o; o >>= 1) ss += __shfl_xor_sync(0xffffffffu, ss, o);
    float rstd = rsqrtf(ss * (1.0f / 256.0f) + LN_EPS);

    float4 g0 = *(const float4*)&g[c],  g1 = *(const float4*)&g[c + 4];
    float4 e0 = *(const float4*)&be[c], e1 = *(const float4*)&be[c + 4];
    *(float4*)&d_dwconv[(size_t)pix * DIM + c]     = make_float4(val[0], val[1], val[2], val[3]);
    *(float4*)&d_dwconv[(size_t)pix * DIM + c + 4] = make_float4(val[4], val[5], val[6], val[7]);

    float n[8];
    n[0]=(val[0]-mean)*rstd*g0.x+e0.x; n[1]=(val[1]-mean)*rstd*g0.y+e0.y;
    n[2]=(val[2]-mean)*rstd*g0.z+e0.z; n[3]=(val[3]-mean)*rstd*g0.w+e0.w;
    n[4]=(val[4]-mean)*rstd*g1.x+e1.x; n[5]=(val[5]-mean)*rstd*g1.y+e1.y;
    n[6]=(val[6]-mean)*rstd*g1.z+e1.z; n[7]=(val[7]-mean)*rstd*g1.w+e1.w;
    __half2 h0 = __floats2half2_rn(n[0], n[1]);
    __half2 h1 = __floats2half2_rn(n[2], n[3]);
    __half2 h2 = __floats2half2_rn(n[4], n[5]);
    __half2 h3 = __floats2half2_rn(n[6], n[7]);
    uint4 u;
    u.x = *(uint32_t*)&h0; u.y = *(uint32_t*)&h1;
    u.z = *(uint32_t*)&h2; u.w = *(uint32_t*)&h3;
    *(uint4*)&d_norm1h[(size_t)pix * DIM + c] = u;
}

// ------- tf32 GEMM (R10 config, proj only): BM=128 BN=128, 2 CTA/SM ----------
// MODE 1: BN( +bias +add1 ) -> fp16 merged
#define TG_BOFF  49152
#define TG_SMEM  98304

template<int KDIM, int MODE, bool PERBATCH>
__global__ void __launch_bounds__(256, 2)
tgemm2(const float* __restrict__ A, int lda,
       const float* __restrict__ Bt,
       float* __restrict__ C, int ldc, int m_off,
       const float* __restrict__ bias, const float* __restrict__ add1,
       const float* __restrict__ bn_g, const float* __restrict__ bn_b,
       const float* __restrict__ bn_m, const float* __restrict__ bn_v)
{
    extern __shared__ char smem[];
    const uint32_t sb = (uint32_t)__cvta_generic_to_shared(smem);
    const int tid  = threadIdx.x;
    const int lane = tid & 31;
    const int w    = tid >> 5;
    const int wm   = w >> 2;
    const int wn   = w & 3;

    int m0, mrows;
    if (PERBATCH) {
        int batch = blockIdx.y / 25;
        int bt    = blockIdx.y % 25;
        m0 = batch * NPIX + bt * 128;
        mrows = min(128, NPIX - bt * 128);
    } else {
        m0 = m_off + blockIdx.y * 128; mrows = 128;
    }
    const int n0 = blockIdx.x * 128;
    const float* Bp = PERBATCH ? (Bt + (size_t)(blockIdx.y / 25) * 65536) : Bt;

    float acc[4][4][4];
    #pragma unroll
    for (int mi = 0; mi < 4; mi++)
        #pragma unroll
        for (int ni = 0; ni < 4; ni++)
            #pragma unroll
            for (int q = 0; q < 4; q++) acc[mi][ni][q] = 0.f;

    auto load_stage = [&](int st) {
        int slot = st % 3;
        int k0 = st * 32;
        #pragma unroll
        for (int i = 0; i < 4; i++) {
            int lin = tid + 256 * i;
            int r = lin >> 3, ch = lin & 7;
            int rg = m0 + (r < mrows ? r : mrows - 1);
            cp_async16_s(sb + slot * 16384 + r * 128 + ((ch ^ (r & 7)) << 4),
                         A + (size_t)rg * lda + k0 + ch * 4);
        }
        #pragma unroll
        for (int i = 0; i < 4; i++) {
            int lin = tid + 256 * i;
            int r = lin >> 3, ch = lin & 7;
            cp_async16_s(sb + TG_BOFF + slot * 16384 + r * 128 + ((ch ^ (r & 7)) << 4),
                         Bp + (size_t)(n0 + r) * KDIM + k0 + ch * 4);
        }
        cp_commit();
    };

    const int KT = KDIM / 32;
    load_stage(0); load_stage(1);

    const int arow_l = (lane & 7) + ((lane >> 3) & 1) * 8;
    const int akoff  = lane >> 4;
    const int brow_l = (lane & 7) + (lane >> 4) * 8;
    const int bkoff  = (lane >> 3) & 1;
    const int sx     = lane & 7;

    for (int s = 0; s < KT; s++) {
        int slot = s % 3;
        if (s < KT - 1) asm volatile("cp.async.wait_group 1;\n" ::: "memory");
        else            asm volatile("cp.async.wait_group 0;\n" ::: "memory");
        __syncthreads();
        if (s + 2 < KT) load_stage(s + 2);

        uint32_t aBase = sb + slot * 16384 + (wm * 64) * 128;
        uint32_t bBase = sb + TG_BOFF + slot * 16384 + (wn * 32) * 128;

        #pragma unroll
        for (int kc = 0; kc < 4; kc++) {
            uint32_t a[4][4];
            #pragma unroll
            for (int mi = 0; mi < 4; mi++)
                ldsm_x4(a[mi], aBase + (mi * 16 + arow_l) * 128
                               + (((2 * kc + akoff) ^ sx) << 4));
            uint32_t bf[2][4];
            #pragma unroll
            for (int nj = 0; nj < 2; nj++)
                ldsm_x4(bf[nj], bBase + (nj * 16 + brow_l) * 128
                                + (((2 * kc + bkoff) ^ sx) << 4));
            #pragma unroll
            for (int mi = 0; mi < 4; mi++)
                #pragma unroll
                for (int ni = 0; ni < 4; ni++)
                    mma_tf32(acc[mi][ni], a[mi],
                             bf[ni >> 1][(ni & 1) * 2], bf[ni >> 1][(ni & 1) * 2 + 1]);
        }
    }

    #pragma unroll
    for (int mi = 0; mi < 4; mi++) {
        #pragma unroll
        for (int h = 0; h < 2; h++) {
            int lr = wm * 64 + mi * 16 + (lane >> 2) + h * 8;
            if (PERBATCH && lr >= mrows) continue;
            size_t grow = (size_t)(m0 + lr);

            #pragma unroll
            for (int ni = 0; ni < 4; ni++) {
                float v0 = acc[mi][ni][2 * h], v1 = acc[mi][ni][2 * h + 1];
                int gc = n0 + wn * 32 + ni * 8 + (lane & 3) * 2;
                if (MODE == 1) {
                    float2 ad = *(const float2*)&add1[grow * 256 + gc];
                    v0 += bias[gc]     + ad.x;
                    v1 += bias[gc + 1] + ad.y;
                    v0 = (v0 - bn_m[gc    ]) * rsqrtf(bn_v[gc    ] + BN_EPS) * bn_g[gc    ] + bn_b[gc    ];
                    v1 = (v1 - bn_m[gc + 1]) * rsqrtf(bn_v[gc + 1] + BN_EPS) * bn_g[gc + 1] + bn_b[gc + 1];
                    *(__half2*)((__half*)C + grow * ldc + gc) = __floats2half2_rn(v0, v1);
                    continue;
                }
                *(float2*)&C[grow * ldc + gc] = make_float2(v0, v1);
            }
        }
    }
}

// -------- fp16 GEMM: BM=128 BN=128 BK=32, 4-stage single-barrier --------------
// MODE 2: gelu(+bias) -> half   MODE 3: +bias +add1 -> float
// MODE 4: qkv: per-head l2norm; qT/kT fp32 transposed (smem-staged), v fp32 dense
#define HG_STAGE 10240
#define HG_B_OFF 40960
#define HG_SMEM  81920

template<int KDIM, int MODE>
__global__ void __launch_bounds__(256, 2)
hgemm(const __half* __restrict__ A,
      const __half* __restrict__ Bt,
      void* __restrict__ Cv, int ldc, int m_off,
      const float* __restrict__ bias, const float* __restrict__ add1)
{
    extern __shared__ char smem[];
    const uint32_t sb = (uint32_t)__cvta_generic_to_shared(smem);
    const int tid  = threadIdx.x;
    const int lane = tid & 31;
    const int w    = tid >> 5;
    const int wm   = w >> 2;
    const int wn   = w & 3;

    const int m0 = m_off + blockIdx.y * 128;
    const int n0 = blockIdx.x * 128;

    float acc[4][4][4];
    #pragma unroll
    for (int mi = 0; mi < 4; mi++)
        #pragma unroll
        for (int ni = 0; ni < 4; ni++)
            #pragma unroll
            for (int q = 0; q < 4; q++) acc[mi][ni][q] = 0.f;

    auto load_stage = [&](int st) {
        int slot = st & 3;
        int k0 = st * 32;
        int r  = tid >> 1;
        int ch = (tid & 1);
        {
            const __half* gp = A + (size_t)(m0 + r) * KDIM + k0 + ch * 16;
            uint32_t dst = sb + slot * HG_STAGE + r * 80 + ch * 32;
            cp_async16_s(dst, gp);
            cp_async16_s(dst + 16, gp + 8);
        }
        {
            const __half* gp = Bt + (size_t)(n0 + r) * KDIM + k0 + ch * 16;
            uint32_t dst = sb + HG_B_OFF + slot * HG_STAGE + r * 80 + ch * 32;
            cp_async16_s(dst, gp);
            cp_async16_s(dst + 16, gp + 8);
        }
        cp_commit();
    };

    const int KT = KDIM / 32;
    load_stage(0); load_stage(1); load_stage(2);

    for (int s = 0; s < KT; s++) {
        int slot = s & 3;
        if (s < KT - 2)       asm volatile("cp.async.wait_group 2;\n" ::: "memory");
        else if (s == KT - 2) asm volatile("cp.async.wait_group 1;\n" ::: "memory");
        else                  asm volatile("cp.async.wait_group 0;\n" ::: "memory");
        __syncthreads();
        if (s + 3 < KT) load_stage(s + 3);

        uint32_t aBase = sb + slot * HG_STAGE + (wm * 64) * 80;
        uint32_t bBase = sb + HG_B_OFF + slot * HG_STAGE + (wn * 32) * 80;
        #pragma unroll
        for (int ks = 0; ks < 2; ks++) {
            const int kc = ks * 2;
            uint32_t a[4][4];
            #pragma unroll
            for (int mi = 0; mi < 4; mi++) {
                uint32_t addr = aBase + (mi * 16 + (lane & 15)) * 80
                              + (kc + (lane >> 4)) * 16;
                ldsm_x4(a[mi], addr);
            }
            uint32_t bf[2][4];
            #pragma unroll
            for (int nj = 0; nj < 2; nj++) {
                uint32_t addr = bBase + (nj * 16 + ((lane >> 4) << 3) + (lane & 7)) * 80
                              + (kc + ((lane >> 3) & 1)) * 16;
                ldsm_x4(bf[nj], addr);
            }
            #pragma unroll
            for (int mi = 0; mi < 4; mi++)
                #pragma unroll
                for (int ni = 0; ni < 4; ni++)
                    mma_f16(acc[mi][ni], a[mi],
                            bf[ni >> 1][(ni & 1) * 2], bf[ni >> 1][(ni & 1) * 2 + 1]);
        }
    }

    // ---- MODE 4 q/k path: l2norm + smem-staged transposed fp32 store ----
    if (MODE == 4 && n0 < 512) {
        float* sT = (float*)smem;             // [col 128][row 128], stride 132
        __syncthreads();
        #pragma unroll
        for (int mi = 0; mi < 4; mi++) {
            #pragma unroll
            for (int h = 0; h < 2; h++) {
                float ss = 0.f;
                #pragma unroll
                for (int ni = 0; ni < 4; ni++) {
                    float v0 = acc[mi][ni][2 * h], v1 = acc[mi][ni][2 * h + 1];
                    ss += v0 * v0 + v1 * v1;
                }
                ss += __shfl_xor_sync(0xffffffffu, ss, 1);
                ss += __shfl_xor_sync(0xffffffffu, ss, 2);
                float sc = rsqrtf(fmaxf(ss, L2_EPS));
                if (n0 < 256) sc *= SCALE_Q;

                int rowl = wm * 64 + mi * 16 + (lane >> 2) + h * 8;
                #pragma unroll
                for (int ni = 0; ni < 4; ni++) {
                    int dl = wn * 32 + ni * 8 + (lane & 3) * 2;
                    sT[dl * 132 + rowl]       = acc[mi][ni][2 * h] * sc;
                    sT[(dl + 1) * 132 + rowl] = acc[mi][ni][2 * h + 1] * sc;
                }
            }
        }
        __syncthreads();
        float* dstT = (n0 < 256) ? d_qT : d_kT;
        #pragma unroll
        for (int i = 0; i < 16; i++) {
            int idx = tid + i * 256;
            int cl  = idx >> 5;
            int row = (idx & 31) * 4;
            int grow = m0 + row;
            int bb = grow / NPIX;
            int n  = grow - bb * NPIX;        // float4 never straddles batch
            int gcol = n0 + cl;
            int head = (gcol & 255) >> 5;
            int d    = gcol & 31;
            float4 v4 = *(float4*)&sT[cl * 132 + row];
            *(float4*)&dstT[((size_t)(bb * 8 + head) * 32 + d) * NPIX + n] = v4;
        }
        return;
    }

    #pragma unroll
    for (int mi = 0; mi < 4; mi++) {
        #pragma unroll
        for (int h = 0; h < 2; h++) {
            int lr = wm * 64 + mi * 16 + (lane >> 2) + h * 8;
            size_t grow = (size_t)(m0 + lr);
            #pragma unroll
            for (int ni = 0; ni < 4; ni++) {
                float v0 = acc[mi][ni][2 * h], v1 = acc[mi][ni][2 * h + 1];
                if (MODE == 4) {
                    // v block (n0 >= 512): fp32 dense store, ldc = 256
                    int gc = (n0 - 512) + wn * 32 + ni * 8 + (lane & 3) * 2;
                    *(float2*)&((float*)Cv)[grow * ldc + gc] = make_float2(v0, v1);
                    continue;
                }
                int gc = n0 + wn * 32 + ni * 8 + (lane & 3) * 2;
                if (MODE == 2) {
                    v0 += bias[gc];   v1 += bias[gc + 1];
                    v0 = 0.5f * v0 * (1.0f + erff(v0 * 0.70710678118654752f));
                    v1 = 0.5f * v1 * (1.0f + erff(v1 * 0.70710678118654752f));
                    *(__half2*)((__half*)Cv + grow * ldc + gc) = __floats2half2_rn(v0, v1);
                } else {
                    float2 ad = *(const float2*)&add1[grow * 256 + gc];
                    v0 += bias[gc]     + ad.x;
                    v1 += bias[gc + 1] + ad.y;
                    *(float2*)&((float*)Cv)[grow * ldc + gc] = make_float2(v0, v1);
                }
            }
        }
    }
}

// ------- attn split-K: per (b,h,split) partial 32x32 q^T k via tf32 mma ------
#define AS_SMEM 24576

__global__ void __launch_bounds__(256) attn_split_kernel()
{
    extern __shared__ char smem[];
    const uint32_t sb = (uint32_t)__cvta_generic_to_shared(smem);
    const int bh = blockIdx.x;
    const int split = blockIdx.y;
    const int tid = threadIdx.x, lane = tid & 31, w = tid >> 5;
    const int wm = w >> 2, wn = w & 3;

    const float* qT = d_qT + (size_t)bh * 32 * NPIX + split * 224;
    const float* kT = d_kT + (size_t)bh * 32 * NPIX + split * 224;

    float c[4] = {0.f, 0.f, 0.f, 0.f};

    auto load_stage = [&](int st) {
        int slot = st % 3;
        int k0 = st * 32;
        int r = tid >> 3, ch = tid & 7;
        uint32_t dst = sb + slot * 8192 + r * 128 + ((ch ^ (r & 7)) << 4);
        cp_async16_s(dst,        qT + (size_t)r * NPIX + k0 + ch * 4);
        cp_async16_s(dst + 4096, kT + (size_t)r * NPIX + k0 + ch * 4);
        cp_commit();
    };

    const int KT = 7;
    load_stage(0); load_stage(1);

    const int arow_l = (lane & 7) + ((lane >> 3) & 1) * 8;
    const int akoff  = lane >> 4;
    const int brow_l = (lane & 7) + (lane >> 4) * 8;
    const int bkoff  = (lane >> 3) & 1;
    const int sx     = lane & 7;
    const int nj     = wn >> 1;
    const int nsel   = (wn & 1) * 2;

    for (int s = 0; s < KT; s++) {
        int slot = s % 3;
        if (s < KT - 1) asm volatile("cp.async.wait_group 1;\n" ::: "memory");
        else            asm volatile("cp.async.wait_group 0;\n" ::: "memory");
        __syncthreads();
        if (s + 2 < KT) load_stage(s + 2);

        uint32_t aBase = sb + slot * 8192 + (wm * 16) * 128;
        uint32_t bBase = sb + slot * 8192 + 4096;
        #pragma unroll
        for (int kc = 0; kc < 4; kc++) {
            uint32_t a[4], bf[4];
            ldsm_x4(a,  aBase + arow_l * 128 + (((2 * kc + akoff) ^ sx) << 4));
            ldsm_x4(bf, bBase + (nj * 16 + brow_l) * 128 + (((2 * kc + bkoff) ^ sx) << 4));
            mma_tf32(c, a, bf[nsel], bf[nsel + 1]);
        }
    }

    float* dst = d_attn_part + ((size_t)split * 128 + bh) * 1024;
    int row = wm * 16 + (lane >> 2);
    int col = wn * 8 + (lane & 3) * 2;
    dst[row * 32 + col]           = c[0];
    dst[row * 32 + col + 1]       = c[1];
    dst[(row + 8) * 32 + col]     = c[2];
    dst[(row + 8) * 32 + col + 1] = c[3];
}

// ------- attn finalize + softmax + wbT = (blockdiag attn @ proj_w)^T ---------
__global__ void __launch_bounds__(1024) attn_wb_kernel(const float* __restrict__ proj_w)
{
    int bh = blockIdx.x;
    int b = bh >> 3, h = bh & 7;
    int tid = threadIdx.x;
    int e = tid & 31, d = tid >> 5;

    __shared__ float sA[32][33];
    __shared__ float sW[32][256];

    float acc = 0.f;
    #pragma unroll
    for (int s = 0; s < NSPLIT; s++)
        acc += d_attn_part[((size_t)s * 128 + bh) * 1024 + d * 32 + e];

    float m = acc;
    #pragma unroll
    for (int o = 16; o; o >>= 1) m = fmaxf(m, __shfl_xor_sync(0xffffffffu, m, o));
    float ex = expf(acc - m);
    float sum = ex;
    #pragma unroll
    for (int o = 16; o; o >>= 1) sum += __shfl_xor_sync(0xffffffffu, sum, o);
    sA[d][e] = ex / sum;

    #pragma unroll
    for (int idx = tid; idx < 8192; idx += 1024)
        sW[idx >> 8][idx & 255] = proj_w[(h * 32 + (idx >> 8)) * 256 + (idx & 255)];
    __syncthreads();

    #pragma unroll
    for (int idx = tid; idx < 8192; idx += 1024) {
        int d2 = idx & 31, c = idx >> 5;
        float s = 0.f;
        #pragma unroll
        for (int ee = 0; ee < 32; ee++) s += sA[d2][ee] * sW[ee][c];
        d_wbT[(size_t)b * 65536 + c * 256 + h * 32 + d2] = s;
    }
}

// ---------------- launch ------------------------------------------------------
extern "C" void kernel_launch(void* const* d_in, const int* in_sizes, int n_in,
                              void* d_out, int out_size)
{
    const float* x        = (const float*)d_in[0];
    const float* dw_kernel= (const float*)d_in[1];
    const float* dw_bias  = (const float*)d_in[2];
    const float* ln_gamma = (const float*)d_in[3];
    const float* ln_beta  = (const float*)d_in[4];
    const float* qkv_w    = (const float*)d_in[5];
    const float* proj_w   = (const float*)d_in[6];
    const float* proj_b   = (const float*)d_in[7];
    const float* bn_gamma = (const float*)d_in[8];
    const float* bn_beta  = (const float*)d_in[9];
    const float* bn_mean  = (const float*)d_in[10];
    const float* bn_var   = (const float*)d_in[11];
    const float* fc1_w    = (const float*)d_in[12];
    const float* fc1_b    = (const float*)d_in[13];
    const float* fc2_w    = (const float*)d_in[14];
    const float* fc2_b    = (const float*)d_in[15];
    float* out = (float*)d_out;

    float  *p_dwconv, *p_v, *p_wbT;
    __half *p_norm1h, *p_mergedh, *p_h1h, *p_qkvTh, *p_fc1T, *p_fc2T;
    cudaGetSymbolAddress((void**)&p_dwconv,  d_dwconv);
    cudaGetSymbolAddress((void**)&p_norm1h,  d_norm1h);
    cudaGetSymbolAddress((void**)&p_v,       d_v);
    cudaGetSymbolAddress((void**)&p_wbT,     d_wbT);
    cudaGetSymbolAddress((void**)&p_mergedh, d_mergedh);
    cudaGetSymbolAddress((void**)&p_h1h,     d_h1h);
    cudaGetSymbolAddress((void**)&p_qkvTh,   d_qkvTh);
    cudaGetSymbolAddress((void**)&p_fc1T,    d_fc1T);
    cudaGetSymbolAddress((void**)&p_fc2T,    d_fc2T);

    cudaFuncSetAttribute(tgemm2<256, 1, true>,
                         cudaFuncAttributeMaxDynamicSharedMemorySize, TG_SMEM);
    cudaFuncSetAttribute(hgemm<256, 4>,
                         cudaFuncAttributeMaxDynamicSharedMemorySize, HG_SMEM);
    cudaFuncSetAttribute(hgemm<256, 2>,
                         cudaFuncAttributeMaxDynamicSharedMemorySize, HG_SMEM);
    cudaFuncSetAttribute(hgemm<1024, 3>,
                         cudaFuncAttributeMaxDynamicSharedMemorySize, HG_SMEM);

    // 1) transpose weights (all fp16)
    transpose3_kernel<<<dim3(32, 32, 3), 256>>>(qkv_w, fc1_w, fc2_w);

    // 2) dwconv + cumsum + LN (dwconv fp32, norm1 fp16)
    dwln_kernel<<<NTOK / 8, 256>>>(x, dw_kernel, dw_bias, ln_gamma, ln_beta);

    // 3) qkv GEMM (fp16 mma), two half-M launches; outputs qT/kT/v fp32
    hgemm<256, 4><<<dim3(6, 196), 256, HG_SMEM>>>(
        p_norm1h, p_qkvTh, p_v, 256, 0, nullptr, nullptr);
    hgemm<256, 4><<<dim3(6, 196), 256, HG_SMEM>>>(
        p_norm1h, p_qkvTh, p_v, 256, NTOK / 2, nullptr, nullptr);

    // 4) attn partials (tf32 mma, split-K x14) — unchanged
    attn_split_kernel<<<dim3(BATCH * HEADS, NSPLIT), 256, AS_SMEM>>>();

    // 5) softmax + wbT — unchanged
    attn_wb_kernel<<<BATCH * HEADS, 1024>>>(proj_w);

    // 6) merged = BN( v @ W_b + proj_b + dwconv ) -> fp16   (tf32 GEMM)
    tgemm2<256, 1, true><<<dim3(2, BATCH * 25), 256, TG_SMEM>>>(
        p_v, 256, p_wbT, (float*)p_mergedh, 256, 0,
        proj_b, p_dwconv, bn_gamma, bn_beta, bn_mean, bn_var);

    // 7) h1 = gelu(merged @ fc1_w + fc1_b) -> fp16          (fp16 GEMM)
    hgemm<256, 2><<<dim3(8, NTOK / 128), 256, HG_SMEM>>>(
        p_mergedh, p_fc1T, p_h1h, 1024, 0, fc1_b, nullptr);

    // 8) out = h1 @ fc2_w + fc2_b + x -> fp32               (fp16 GEMM)
    hgemm<1024, 3><<<dim3(2, NTOK / 128), 256, HG_SMEM>>>(
        p_h1h, p_fc2T, out, 256, 0, fc2_b, x);
}

// round 14
// speedup vs baseline: 1.4301x; 1.0645x over previous
#include <cuda_runtime.h>
#include <cuda_fp16.h>
#include <cstdint>
#include <math.h>

#define DIM     256
#define HEADS   8
#define HDIM    32
#define GW      64
#define HW      56
#define NPIX    3136            // 56*56
#define BATCH   16
#define NTOK    (BATCH * NPIX)  // 50176
#define HIDDEN  1024
#define LN_EPS  1e-6f
#define BN_EPS  1e-3f
#define L2_EPS  1e-12f
#define SCALE_Q 0.17677669529663689f  // 32^-0.5
#define NSPLIT  14                     // 3136 = 14 * 224

// ---------------- scratch (static device globals; no cudaMalloc) -------------
__device__ __align__(16) float  d_dwconv   [NTOK * DIM];
__device__ __align__(16) __half d_norm1h   [NTOK * DIM];
__device__ __align__(16) __half d_qTh      [BATCH * HEADS * HDIM * NPIX]; // [b][h][d][n]
__device__ __align__(16) __half d_kTh      [BATCH * HEADS * HDIM * NPIX];
__device__ __align__(16) __half d_vh       [NTOK * DIM];
__device__ __align__(16) float  d_attn_part[NSPLIT * BATCH * HEADS * HDIM * HDIM];
__device__ __align__(16) __half d_wbTh     [BATCH * DIM * DIM];   // [b][c][h*32+d]
__device__ __align__(16) __half d_mergedh  [NTOK * DIM];
__device__ __align__(16) __half d_h1h      [NTOK * HIDDEN];
__device__ __align__(16) __half d_qkvTh    [768 * 256];
__device__ __align__(16) __half d_fc1T     [1024 * 256];
__device__ __align__(16) __half d_fc2T     [256 * 1024];

// ---------------- PTX helpers -------------------------------------------------
__device__ __forceinline__ void cp_async16_s(uint32_t saddr, const void* gptr) {
    asm volatile("cp.async.cg.shared.global [%0], [%1], 16;\n" :: "r"(saddr), "l"(gptr));
}
__device__ __forceinline__ void cp_commit() { asm volatile("cp.async.commit_group;\n"); }

__device__ __forceinline__ void ldsm_x4(uint32_t r[4], uint32_t addr) {
    asm volatile("ldmatrix.sync.aligned.m8n8.x4.shared.b16 {%0,%1,%2,%3}, [%4];"
        : "=r"(r[0]), "=r"(r[1]), "=r"(r[2]), "=r"(r[3]) : "r"(addr));
}
__device__ __forceinline__ void mma_f16(float c[4], const uint32_t a[4],
                                        uint32_t b0, uint32_t b1) {
    asm volatile(
        "mma.sync.aligned.m16n8k16.row.col.f32.f16.f16.f32 "
        "{%0,%1,%2,%3}, {%4,%5,%6,%7}, {%8,%9}, {%0,%1,%2,%3};"
        : "+f"(c[0]), "+f"(c[1]), "+f"(c[2]), "+f"(c[3])
        : "r"(a[0]), "r"(a[1]), "r"(a[2]), "r"(a[3]), "r"(b0), "r"(b1));
}

// ------- kernel 0: transpose weights -> fp16 [N, K] ---------------------------
__global__ void __launch_bounds__(256) transpose3_kernel(
    const float* __restrict__ qkv_w, const float* __restrict__ fc1_w,
    const float* __restrict__ fc2_w)
{
    const float* src; int R, C;
    if (blockIdx.z == 0)      { src = qkv_w; R = 256;  C = 768;  }
    else if (blockIdx.z == 1) { src = fc1_w; R = 256;  C = 1024; }
    else                      { src = fc2_w; R = 1024; C = 256;  }
    int x0 = blockIdx.x * 32, y0 = blockIdx.y * 32;
    if (x0 >= C || y0 >= R) return;

    __shared__ float t[32][33];
    int tx = threadIdx.x & 31, ty = threadIdx.x >> 5;
    #pragma unroll
    for (int i = ty; i < 32; i += 8)
        t[i][tx] = src[(size_t)(y0 + i) * C + x0 + tx];
    __syncthreads();
    #pragma unroll
    for (int i = ty; i < 32; i += 8) {
        if (blockIdx.z == 0)
            d_qkvTh[(size_t)(x0 + i) * R + y0 + tx] = __float2half(t[tx][i]);
        else if (blockIdx.z == 1)
            d_fc1T[(size_t)(x0 + i) * R + y0 + tx] = __float2half(t[tx][i]);
        else
            d_fc2T[(size_t)(x0 + i) * R + y0 + tx] = __float2half(t[tx][i]);
    }
}

// ---- kernel 1: dwconv3x3 + group cumsum + LayerNorm, warp-per-pixel ---------
__global__ void __launch_bounds__(256) dwln_kernel(
    const float* __restrict__ x, const float* __restrict__ dwk,
    const float* __restrict__ dwb, const float* __restrict__ g,
    const float* __restrict__ be)
{
    const int lane = threadIdx.x & 31;
    const int wrp  = threadIdx.x >> 5;
    const int pix  = blockIdx.x * 8 + wrp;
    const int b  = pix / NPIX;
    const int p  = pix - b * NPIX;
    const int hh = p / HW, ww = p - hh * HW;
    const int c  = lane * 8;

    float val[8];
    if (lane < 8) {
        float4 a0 = *(const float4*)&x[(size_t)pix * DIM + c];
        float4 a1 = *(const float4*)&x[(size_t)pix * DIM + c + 4];
        val[0]=a0.x; val[1]=a0.y; val[2]=a0.z; val[3]=a0.w;
        val[4]=a1.x; val[5]=a1.y; val[6]=a1.z; val[7]=a1.w;
    } else {
        const int cc = c - GW;
        float4 b0 = *(const float4*)&dwb[cc];
        float4 b1 = *(const float4*)&dwb[cc + 4];
        val[0]=b0.x; val[1]=b0.y; val[2]=b0.z; val[3]=b0.w;
        val[4]=b1.x; val[5]=b1.y; val[6]=b1.z; val[7]=b1.w;
        #pragma unroll
        for (int ky = 0; ky < 3; ky++) {
            int hy = hh + ky - 1;
            if ((unsigned)hy < (unsigned)HW) {
                #pragma unroll
                for (int kx = 0; kx < 3; kx++) {
                    int wx = ww + kx - 1;
                    if ((unsigned)wx < (unsigned)HW) {
                        const float* xp = &x[((size_t)(b * HW + hy) * HW + wx) * DIM + c];
                        const float* wp = &dwk[(ky * 3 + kx) * 192 + cc];
                        float4 x0 = *(const float4*)xp, x1 = *(const float4*)(xp + 4);
                        float4 w0 = *(const float4*)wp, w1 = *(const float4*)(wp + 4);
                        val[0] += x0.x * w0.x; val[1] += x0.y * w0.y;
                        val[2] += x0.z * w0.z; val[3] += x0.w * w0.w;
                        val[4] += x1.x * w1.x; val[5] += x1.y * w1.y;
                        val[6] += x1.z * w1.z; val[7] += x1.w * w1.w;
                    }
                }
            }
        }
    }

    {
        const int s0 = 8 + (lane & 7);
        const int gi = (lane >> 3) - 1;
        #pragma unroll
        for (int i = 0; i < 8; i++) {
            float k0 = __shfl_sync(0xffffffffu, val[i], s0);
            float k1 = __shfl_sync(0xffffffffu, val[i], s0 + 8);
            float k2 = __shfl_sync(0xffffffffu, val[i], s0 + 16);
            if (lane >= 8) {
                float s = k0;
                if (gi >= 1) s += k1;
                if (gi >= 2) s += k2;
                val[i] = s;
            }
        }
    }

    float sum = 0.f;
    #pragma unroll
    for (int i = 0; i < 8; i++) sum += val[i];
    #pragma unroll
    for (int o = 16; o; o >>= 1) sum += __shfl_xor_sync(0xffffffffu, sum, o);
    float mean = sum * (1.0f / 256.0f);

    float ss = 0.f;
    #pragma unroll
    for (int i = 0; i < 8; i++) { float d = val[i] - mean; ss += d * d; }
    #pragma unroll
    for (int o = 16; o; o >>= 1) ss += __shfl_xor_sync(0xffffffffu, ss, o);
    float rstd = rsqrtf(ss * (1.0f / 256.0f) + LN_EPS);

    float4 g0 = *(const float4*)&g[c],  g1 = *(const float4*)&g[c + 4];
    float4 e0 = *(const float4*)&be[c], e1 = *(const float4*)&be[c + 4];
    *(float4*)&d_dwconv[(size_t)pix * DIM + c]     = make_float4(val[0], val[1], val[2], val[3]);
    *(float4*)&d_dwconv[(size_t)pix * DIM + c + 4] = make_float4(val[4], val[5], val[6], val[7]);

    float n[8];
    n[0]=(val[0]-mean)*rstd*g0.x+e0.x; n[1]=(val[1]-mean)*rstd*g0.y+e0.y;
    n[2]=(val[2]-mean)*rstd*g0.z+e0.z; n[3]=(val[3]-mean)*rstd*g0.w+e0.w;
    n[4]=(val[4]-mean)*rstd*g1.x+e1.x; n[5]=(val[5]-mean)*rstd*g1.y+e1.y;
    n[6]=(val[6]-mean)*rstd*g1.z+e1.z; n[7]=(val[7]-mean)*rstd*g1.w+e1.w;
    __half2 h0 = __floats2half2_rn(n[0], n[1]);
    __half2 h1 = __floats2half2_rn(n[2], n[3]);
    __half2 h2 = __floats2half2_rn(n[4], n[5]);
    __half2 h3 = __floats2half2_rn(n[6], n[7]);
    uint4 u;
    u.x = *(uint32_t*)&h0; u.y = *(uint32_t*)&h1;
    u.z = *(uint32_t*)&h2; u.w = *(uint32_t*)&h3;
    *(uint4*)&d_norm1h[(size_t)pix * DIM + c] = u;
}

// -------- fp16 GEMM: BM=128 BN=128 BK=32, 4-stage single-barrier --------------
// MODE 1: BN( +bias +add1 fp32 ) -> half (proj, PERBATCH)
// MODE 2: gelu(+bias) -> half (fc1)     MODE 3: +bias +add1 -> float (fc2)
// MODE 4: qkv: per-head l2norm; qTh/kTh fp16 transposed (smem-staged), vh dense
#define HG_STAGE 10240
#define HG_B_OFF 40960
#define HG_SMEM  81920

template<int KDIM, int MODE, bool PERBATCH>
__global__ void __launch_bounds__(256, 2)
hgemm(const __half* __restrict__ A,
      const __half* __restrict__ Bt,
      void* __restrict__ Cv, int ldc, int m_off,
      const float* __restrict__ bias, const float* __restrict__ add1,
      const float* __restrict__ bn_g, const float* __restrict__ bn_b,
      const float* __restrict__ bn_m, const float* __restrict__ bn_v)
{
    extern __shared__ char smem[];
    const uint32_t sb = (uint32_t)__cvta_generic_to_shared(smem);
    const int tid  = threadIdx.x;
    const int lane = tid & 31;
    const int w    = tid >> 5;
    const int wm   = w >> 2;
    const int wn   = w & 3;

    int m0, mrows;
    if (PERBATCH) {
        int batch = blockIdx.y / 25;
        int bt    = blockIdx.y % 25;
        m0 = batch * NPIX + bt * 128;
        mrows = min(128, NPIX - bt * 128);
    } else {
        m0 = m_off + blockIdx.y * 128; mrows = 128;
    }
    const int n0 = blockIdx.x * 128;
    const __half* Bp = PERBATCH ? (Bt + (size_t)(blockIdx.y / 25) * 65536) : Bt;

    float acc[4][4][4];
    #pragma unroll
    for (int mi = 0; mi < 4; mi++)
        #pragma unroll
        for (int ni = 0; ni < 4; ni++)
            #pragma unroll
            for (int q = 0; q < 4; q++) acc[mi][ni][q] = 0.f;

    auto load_stage = [&](int st) {
        int slot = st & 3;
        int k0 = st * 32;
        int r  = tid >> 1;
        int ch = (tid & 1);
        {
            int rg = m0 + (r < mrows ? r : mrows - 1);
            const __half* gp = A + (size_t)rg * KDIM + k0 + ch * 16;
            uint32_t dst = sb + slot * HG_STAGE + r * 80 + ch * 32;
            cp_async16_s(dst, gp);
            cp_async16_s(dst + 16, gp + 8);
        }
        {
            const __half* gp = Bp + (size_t)(n0 + r) * KDIM + k0 + ch * 16;
            uint32_t dst = sb + HG_B_OFF + slot * HG_STAGE + r * 80 + ch * 32;
            cp_async16_s(dst, gp);
            cp_async16_s(dst + 16, gp + 8);
        }
        cp_commit();
    };

    const int KT = KDIM / 32;
    load_stage(0); load_stage(1); load_stage(2);

    for (int s = 0; s < KT; s++) {
        int slot = s & 3;
        if (s < KT - 2)       asm volatile("cp.async.wait_group 2;\n" ::: "memory");
        else if (s == KT - 2) asm volatile("cp.async.wait_group 1;\n" ::: "memory");
        else                  asm volatile("cp.async.wait_group 0;\n" ::: "memory");
        __syncthreads();
        if (s + 3 < KT) load_stage(s + 3);

        uint32_t aBase = sb + slot * HG_STAGE + (wm * 64) * 80;
        uint32_t bBase = sb + HG_B_OFF + slot * HG_STAGE + (wn * 32) * 80;
        #pragma unroll
        for (int ks = 0; ks < 2; ks++) {
            const int kc = ks * 2;
            uint32_t a[4][4];
            #pragma unroll
            for (int mi = 0; mi < 4; mi++) {
                uint32_t addr = aBase + (mi * 16 + (lane & 15)) * 80
                              + (kc + (lane >> 4)) * 16;
                ldsm_x4(a[mi], addr);
            }
            uint32_t bf[2][4];
            #pragma unroll
            for (int nj = 0; nj < 2; nj++) {
                uint32_t addr = bBase + (nj * 16 + ((lane >> 4) << 3) + (lane & 7)) * 80
                              + (kc + ((lane >> 3) & 1)) * 16;
                ldsm_x4(bf[nj], addr);
            }
            #pragma unroll
            for (int mi = 0; mi < 4; mi++)
                #pragma unroll
                for (int ni = 0; ni < 4; ni++)
                    mma_f16(acc[mi][ni], a[mi],
                            bf[ni >> 1][(ni & 1) * 2], bf[ni >> 1][(ni & 1) * 2 + 1]);
        }
    }

    // ---- MODE 4 q/k path: l2norm + smem-staged transposed fp16 store ----
    if (MODE == 4 && n0 < 512) {
        float* sT = (float*)smem;             // [col 128][row 128], stride 132
        __syncthreads();
        #pragma unroll
        for (int mi = 0; mi < 4; mi++) {
            #pragma unroll
            for (int h = 0; h < 2; h++) {
                float ss = 0.f;
                #pragma unroll
                for (int ni = 0; ni < 4; ni++) {
                    float v0 = acc[mi][ni][2 * h], v1 = acc[mi][ni][2 * h + 1];
                    ss += v0 * v0 + v1 * v1;
                }
                ss += __shfl_xor_sync(0xffffffffu, ss, 1);
                ss += __shfl_xor_sync(0xffffffffu, ss, 2);
                float sc = rsqrtf(fmaxf(ss, L2_EPS));
                if (n0 < 256) sc *= SCALE_Q;

                int rowl = wm * 64 + mi * 16 + (lane >> 2) + h * 8;
                #pragma unroll
                for (int ni = 0; ni < 4; ni++) {
                    int dl = wn * 32 + ni * 8 + (lane & 3) * 2;
                    sT[dl * 132 + rowl]       = acc[mi][ni][2 * h] * sc;
                    sT[(dl + 1) * 132 + rowl] = acc[mi][ni][2 * h + 1] * sc;
                }
            }
        }
        __syncthreads();
        __half* dstT = (n0 < 256) ? d_qTh : d_kTh;
        #pragma unroll
        for (int i = 0; i < 16; i++) {
            int idx = tid + i * 256;
            int cl  = idx >> 5;
            int row = (idx & 31) * 4;
            int grow = m0 + row;
            int bb = grow / NPIX;
            int n  = grow - bb * NPIX;        // 4-run never straddles batch
            int gcol = n0 + cl;
            int head = (gcol & 255) >> 5;
            int d    = gcol & 31;
            float4 v4 = *(float4*)&sT[cl * 132 + row];
            __half2 p0 = __floats2half2_rn(v4.x, v4.y);
            __half2 p1 = __floats2half2_rn(v4.z, v4.w);
            uint2 u; u.x = *(uint32_t*)&p0; u.y = *(uint32_t*)&p1;
            *(uint2*)&dstT[((size_t)(bb * 8 + head) * 32 + d) * NPIX + n] = u;
        }
        return;
    }

    // ---- epilogue ----
    #pragma unroll
    for (int mi = 0; mi < 4; mi++) {
        #pragma unroll
        for (int h = 0; h < 2; h++) {
            int lr = wm * 64 + mi * 16 + (lane >> 2) + h * 8;
            if (PERBATCH && lr >= mrows) continue;
            size_t grow = (size_t)(m0 + lr);
            #pragma unroll
            for (int ni = 0; ni < 4; ni++) {
                float v0 = acc[mi][ni][2 * h], v1 = acc[mi][ni][2 * h + 1];
                if (MODE == 4) {
                    // v block (n0 >= 512): fp16 dense store, ldc = 256
                    int gc = (n0 - 512) + wn * 32 + ni * 8 + (lane & 3) * 2;
                    *(__half2*)((__half*)Cv + grow * ldc + gc) = __floats2half2_rn(v0, v1);
                    continue;
                }
                int gc = n0 + wn * 32 + ni * 8 + (lane & 3) * 2;
                if (MODE == 1) {
                    float2 ad = *(const float2*)&add1[grow * 256 + gc];
                    v0 += bias[gc]     + ad.x;
                    v1 += bias[gc + 1] + ad.y;
                    v0 = (v0 - bn_m[gc    ]) * rsqrtf(bn_v[gc    ] + BN_EPS) * bn_g[gc    ] + bn_b[gc    ];
                    v1 = (v1 - bn_m[gc + 1]) * rsqrtf(bn_v[gc + 1] + BN_EPS) * bn_g[gc + 1] + bn_b[gc + 1];
                    *(__half2*)((__half*)Cv + grow * ldc + gc) = __floats2half2_rn(v0, v1);
                } else if (MODE == 2) {
                    v0 += bias[gc];   v1 += bias[gc + 1];
                    v0 = 0.5f * v0 * (1.0f + erff(v0 * 0.70710678118654752f));
                    v1 = 0.5f * v1 * (1.0f + erff(v1 * 0.70710678118654752f));
                    *(__half2*)((__half*)Cv + grow * ldc + gc) = __floats2half2_rn(v0, v1);
                } else {
                    float2 ad = *(const float2*)&add1[grow * 256 + gc];
                    v0 += bias[gc]     + ad.x;
                    v1 += bias[gc + 1] + ad.y;
                    *(float2*)&((float*)Cv)[grow * ldc + gc] = make_float2(v0, v1);
                }
            }
        }
    }
}

// ------- attn split-K (fp16 mma): per (b,h,split) partial 32x32 q^T k --------
// Stage: 32 rows x 64B (32 halves) padded to 80B, q + k = 5120B/stage, 3 stages.
#define AS_STAGE 5120
#define AS_SMEM  15360

__global__ void __launch_bounds__(256) attn_split_kernel()
{
    extern __shared__ char smem[];
    const uint32_t sb = (uint32_t)__cvta_generic_to_shared(smem);
    const int bh = blockIdx.x;
    const int split = blockIdx.y;
    const int tid = threadIdx.x, lane = tid & 31, w = tid >> 5;
    const int wm = w >> 2, wn = w & 3;

    const __half* qT = d_qTh + (size_t)bh * 32 * NPIX + split * 224;
    const __half* kT = d_kTh + (size_t)bh * 32 * NPIX + split * 224;

    float c[4] = {0.f, 0.f, 0.f, 0.f};

    auto load_stage = [&](int st) {
        int slot = st % 3;
        int k0 = st * 32;                     // halves
        int op = tid >> 7;                    // 0 = q, 1 = k
        int rr = (tid >> 2) & 31;
        int ch = tid & 3;
        const __half* src = (op ? kT : qT) + (size_t)rr * NPIX + k0 + ch * 8;
        cp_async16_s(sb + slot * AS_STAGE + op * 2560 + rr * 80 + ch * 16, src);
        cp_commit();
    };

    const int KT = 7;                         // 224 / 32
    load_stage(0); load_stage(1);

    const int nj   = wn >> 1;
    const int nsel = (wn & 1) * 2;

    for (int s = 0; s < KT; s++) {
        int slot = s % 3;
        if (s < KT - 1) asm volatile("cp.async.wait_group 1;\n" ::: "memory");
        else            asm volatile("cp.async.wait_group 0;\n" ::: "memory");
        __syncthreads();
        if (s + 2 < KT) load_stage(s + 2);

        uint32_t aBase = sb + slot * AS_STAGE + (wm * 16) * 80;
        uint32_t bBase = sb + slot * AS_STAGE + 2560;
        #pragma unroll
        for (int ks = 0; ks < 2; ks++) {
            const int kc = ks * 2;
            uint32_t a[4], bf[4];
            ldsm_x4(a, aBase + (lane & 15) * 80 + (kc + (lane >> 4)) * 16);
            ldsm_x4(bf, bBase + (nj * 16 + ((lane >> 4) << 3) + (lane & 7)) * 80
                        + (kc + ((lane >> 3) & 1)) * 16);
            mma_f16(c, a, bf[nsel], bf[nsel + 1]);
        }
    }

    float* dst = d_attn_part + ((size_t)split * 128 + bh) * 1024;
    int row = wm * 16 + (lane >> 2);
    int col = wn * 8 + (lane & 3) * 2;
    dst[row * 32 + col]           = c[0];
    dst[row * 32 + col + 1]       = c[1];
    dst[(row + 8) * 32 + col]     = c[2];
    dst[(row + 8) * 32 + col + 1] = c[3];
}

// ------- attn finalize + softmax + wbT^h = (blockdiag attn @ proj_w)^T -------
__global__ void __launch_bounds__(1024) attn_wb_kernel(const float* __restrict__ proj_w)
{
    int bh = blockIdx.x;
    int b = bh >> 3, h = bh & 7;
    int tid = threadIdx.x;
    int e = tid & 31, d = tid >> 5;

    __shared__ float sA[32][33];
    __shared__ float sW[32][256];

    float acc = 0.f;
    #pragma unroll
    for (int s = 0; s < NSPLIT; s++)
        acc += d_attn_part[((size_t)s * 128 + bh) * 1024 + d * 32 + e];

    float m = acc;
    #pragma unroll
    for (int o = 16; o; o >>= 1) m = fmaxf(m, __shfl_xor_sync(0xffffffffu, m, o));
    float ex = expf(acc - m);
    float sum = ex;
    #pragma unroll
    for (int o = 16; o; o >>= 1) sum += __shfl_xor_sync(0xffffffffu, sum, o);
    sA[d][e] = ex / sum;

    #pragma unroll
    for (int idx = tid; idx < 8192; idx += 1024)
        sW[idx >> 8][idx & 255] = proj_w[(h * 32 + (idx >> 8)) * 256 + (idx & 255)];
    __syncthreads();

    #pragma unroll
    for (int idx = tid; idx < 8192; idx += 1024) {
        int d2 = idx & 31, c = idx >> 5;
        float s = 0.f;
        #pragma unroll
        for (int ee = 0; ee < 32; ee++) s += sA[d2][ee] * sW[ee][c];
        d_wbTh[(size_t)b * 65536 + c * 256 + h * 32 + d2] = __float2half(s);
    }
}

// ---------------- launch ------------------------------------------------------
extern "C" void kernel_launch(void* const* d_in, const int* in_sizes, int n_in,
                              void* d_out, int out_size)
{
    const float* x        = (const float*)d_in[0];
    const float* dw_kernel= (const float*)d_in[1];
    const float* dw_bias  = (const float*)d_in[2];
    const float* ln_gamma = (const float*)d_in[3];
    const float* ln_beta  = (const float*)d_in[4];
    const float* qkv_w    = (const float*)d_in[5];
    const float* proj_w   = (const float*)d_in[6];
    const float* proj_b   = (const float*)d_in[7];
    const float* bn_gamma = (const float*)d_in[8];
    const float* bn_beta  = (const float*)d_in[9];
    const float* bn_mean  = (const float*)d_in[10];
    const float* bn_var   = (const float*)d_in[11];
    const float* fc1_w    = (const float*)d_in[12];
    const float* fc1_b    = (const float*)d_in[13];
    const float* fc2_w    = (const float*)d_in[14];
    const float* fc2_b    = (const float*)d_in[15];
    float* out = (float*)d_out;

    float  *p_dwconv;
    __half *p_norm1h, *p_vh, *p_wbTh, *p_mergedh, *p_h1h, *p_qkvTh, *p_fc1T, *p_fc2T;
    cudaGetSymbolAddress((void**)&p_dwconv,  d_dwconv);
    cudaGetSymbolAddress((void**)&p_norm1h,  d_norm1h);
    cudaGetSymbolAddress((void**)&p_vh,      d_vh);
    cudaGetSymbolAddress((void**)&p_wbTh,    d_wbTh);
    cudaGetSymbolAddress((void**)&p_mergedh, d_mergedh);
    cudaGetSymbolAddress((void**)&p_h1h,     d_h1h);
    cudaGetSymbolAddress((void**)&p_qkvTh,   d_qkvTh);
    cudaGetSymbolAddress((void**)&p_fc1T,    d_fc1T);
    cudaGetSymbolAddress((void**)&p_fc2T,    d_fc2T);

    cudaFuncSetAttribute(hgemm<256, 4, false>,
                         cudaFuncAttributeMaxDynamicSharedMemorySize, HG_SMEM);
    cudaFuncSetAttribute(hgemm<256, 1, true>,
                         cudaFuncAttributeMaxDynamicSharedMemorySize, HG_SMEM);
    cudaFuncSetAttribute(hgemm<256, 2, false>,
                         cudaFuncAttributeMaxDynamicSharedMemorySize, HG_SMEM);
    cudaFuncSetAttribute(hgemm<1024, 3, false>,
                         cudaFuncAttributeMaxDynamicSharedMemorySize, HG_SMEM);

    // 1) transpose weights (all fp16)
    transpose3_kernel<<<dim3(32, 32, 3), 256>>>(qkv_w, fc1_w, fc2_w);

    // 2) dwconv + cumsum + LN (dwconv fp32, norm1 fp16)
    dwln_kernel<<<NTOK / 8, 256>>>(x, dw_kernel, dw_bias, ln_gamma, ln_beta);

    // 3) qkv GEMM (fp16), two half-M launches; qTh/kTh/vh fp16 outputs
    hgemm<256, 4, false><<<dim3(6, 196), 256, HG_SMEM>>>(
        p_norm1h, p_qkvTh, p_vh, 256, 0,
        nullptr, nullptr, nullptr, nullptr, nullptr, nullptr);
    hgemm<256, 4, false><<<dim3(6, 196), 256, HG_SMEM>>>(
        p_norm1h, p_qkvTh, p_vh, 256, NTOK / 2,
        nullptr, nullptr, nullptr, nullptr, nullptr, nullptr);

    // 4) attn partials (fp16 mma, split-K x14)
    attn_split_kernel<<<dim3(BATCH * HEADS, NSPLIT), 256, AS_SMEM>>>();

    // 5) softmax + wbT (fp16)
    attn_wb_kernel<<<BATCH * HEADS, 1024>>>(proj_w);

    // 6) merged = BN( v @ W_b + proj_b + dwconv ) -> fp16   (fp16 GEMM, per-batch)
    hgemm<256, 1, true><<<dim3(2, BATCH * 25), 256, HG_SMEM>>>(
        p_vh, p_wbTh, p_mergedh, 256, 0,
        proj_b, p_dwconv, bn_gamma, bn_beta, bn_mean, bn_var);

    // 7) h1 = gelu(merged @ fc1_w + fc1_b) -> fp16
    hgemm<256, 2, false><<<dim3(8, NTOK / 128), 256, HG_SMEM>>>(
        p_mergedh, p_fc1T, p_h1h, 1024, 0,
        fc1_b, nullptr, nullptr, nullptr, nullptr, nullptr);

    // 8) out = h1 @ fc2_w + fc2_b + x -> fp32
    hgemm<1024, 3, false><<<dim3(2, NTOK / 128), 256, HG_SMEM>>>(
        p_h1h, p_fc2T, out, 256, 0,
        fc2_b, x, nullptr, nullptr, nullptr, nullptr);
}

// round 15
// speedup vs baseline: 1.6862x; 1.1791x over previous
#include <cuda_runtime.h>
#include <cuda_fp16.h>
#include <cstdint>
#include <math.h>

#define DIM     256
#define HEADS   8
#define HDIM    32
#define GW      64
#define HW      56
#define NPIX    3136            // 56*56
#define BATCH   16
#define NTOK    (BATCH * NPIX)  // 50176
#define HIDDEN  1024
#define LN_EPS  1e-6f
#define BN_EPS  1e-3f
#define L2_EPS  1e-12f
#define SCALE_Q 0.17677669529663689f  // 32^-0.5
#define NSPLIT  14                     // 3136 = 14 * 224

// ---------------- scratch (static device globals; no cudaMalloc) -------------
__device__ __align__(16) float  d_dwconv   [NTOK * DIM];
__device__ __align__(16) __half d_norm1h   [NTOK * DIM];
__device__ __align__(16) __half d_qTh      [BATCH * HEADS * HDIM * NPIX]; // [b][h][d][n]
__device__ __align__(16) __half d_kTh      [BATCH * HEADS * HDIM * NPIX];
__device__ __align__(16) __half d_vh       [NTOK * DIM];
__device__ __align__(16) float  d_attn_part[NSPLIT * BATCH * HEADS * HDIM * HDIM];
__device__ __align__(16) __half d_wbTh     [BATCH * DIM * DIM];   // [b][c][h*32+d]
__device__ __align__(16) __half d_mergedh  [NTOK * DIM];
__device__ __align__(16) __half d_h1h      [NTOK * HIDDEN];
__device__ __align__(16) __half d_qkvTh    [768 * 256];
__device__ __align__(16) __half d_fc1T     [1024 * 256];
__device__ __align__(16) __half d_fc2T     [256 * 1024];

// ---------------- PTX helpers -------------------------------------------------
__device__ __forceinline__ void cp_async16_s(uint32_t saddr, const void* gptr) {
    asm volatile("cp.async.cg.shared.global [%0], [%1], 16;\n" :: "r"(saddr), "l"(gptr));
}
__device__ __forceinline__ void cp_commit() { asm volatile("cp.async.commit_group;\n"); }

__device__ __forceinline__ void ldsm_x4(uint32_t r[4], uint32_t addr) {
    asm volatile("ldmatrix.sync.aligned.m8n8.x4.shared.b16 {%0,%1,%2,%3}, [%4];"
        : "=r"(r[0]), "=r"(r[1]), "=r"(r[2]), "=r"(r[3]) : "r"(addr));
}
__device__ __forceinline__ void mma_f16(float c[4], const uint32_t a[4],
                                        uint32_t b0, uint32_t b1) {
    asm volatile(
        "mma.sync.aligned.m16n8k16.row.col.f32.f16.f16.f32 "
        "{%0,%1,%2,%3}, {%4,%5,%6,%7}, {%8,%9}, {%0,%1,%2,%3};"
        : "+f"(c[0]), "+f"(c[1]), "+f"(c[2]), "+f"(c[3])
        : "r"(a[0]), "r"(a[1]), "r"(a[2]), "r"(a[3]), "r"(b0), "r"(b1));
}

// ------- kernel 0: transpose weights -> fp16 [N, K] ---------------------------
__global__ void __launch_bounds__(256) transpose3_kernel(
    const float* __restrict__ qkv_w, const float* __restrict__ fc1_w,
    const float* __restrict__ fc2_w)
{
    const float* src; int R, C;
    if (blockIdx.z == 0)      { src = qkv_w; R = 256;  C = 768;  }
    else if (blockIdx.z == 1) { src = fc1_w; R = 256;  C = 1024; }
    else                      { src = fc2_w; R = 1024; C = 256;  }
    int x0 = blockIdx.x * 32, y0 = blockIdx.y * 32;
    if (x0 >= C || y0 >= R) return;

    __shared__ float t[32][33];
    int tx = threadIdx.x & 31, ty = threadIdx.x >> 5;
    #pragma unroll
    for (int i = ty; i < 32; i += 8)
        t[i][tx] = src[(size_t)(y0 + i) * C + x0 + tx];
    __syncthreads();
    #pragma unroll
    for (int i = ty; i < 32; i += 8) {
        if (blockIdx.z == 0)
            d_qkvTh[(size_t)(x0 + i) * R + y0 + tx] = __float2half(t[tx][i]);
        else if (blockIdx.z == 1)
            d_fc1T[(size_t)(x0 + i) * R + y0 + tx] = __float2half(t[tx][i]);
        else
            d_fc2T[(size_t)(x0 + i) * R + y0 + tx] = __float2half(t[tx][i]);
    }
}

// ---- kernel 1: dwconv3x3 + group cumsum + LayerNorm, warp-per-pixel ---------
__global__ void __launch_bounds__(256) dwln_kernel(
    const float* __restrict__ x, const float* __restrict__ dwk,
    const float* __restrict__ dwb, const float* __restrict__ g,
    const float* __restrict__ be)
{
    const int lane = threadIdx.x & 31;
    const int wrp  = threadIdx.x >> 5;
    const int pix  = blockIdx.x * 8 + wrp;
    const int b  = pix / NPIX;
    const int p  = pix - b * NPIX;
    const int hh = p / HW, ww = p - hh * HW;
    const int c  = lane * 8;

    float val[8];
    if (lane < 8) {
        float4 a0 = *(const float4*)&x[(size_t)pix * DIM + c];
        float4 a1 = *(const float4*)&x[(size_t)pix * DIM + c + 4];
        val[0]=a0.x; val[1]=a0.y; val[2]=a0.z; val[3]=a0.w;
        val[4]=a1.x; val[5]=a1.y; val[6]=a1.z; val[7]=a1.w;
    } else {
        const int cc = c - GW;
        float4 b0 = *(const float4*)&dwb[cc];
        float4 b1 = *(const float4*)&dwb[cc + 4];
        val[0]=b0.x; val[1]=b0.y; val[2]=b0.z; val[3]=b0.w;
        val[4]=b1.x; val[5]=b1.y; val[6]=b1.z; val[7]=b1.w;
        #pragma unroll
        for (int ky = 0; ky < 3; ky++) {
            int hy = hh + ky - 1;
            if ((unsigned)hy < (unsigned)HW) {
                #pragma unroll
                for (int kx = 0; kx < 3; kx++) {
                    int wx = ww + kx - 1;
                    if ((unsigned)wx < (unsigned)HW) {
                        const float* xp = &x[((size_t)(b * HW + hy) * HW + wx) * DIM + c];
                        const float* wp = &dwk[(ky * 3 + kx) * 192 + cc];
                        float4 x0 = *(const float4*)xp, x1 = *(const float4*)(xp + 4);
                        float4 w0 = *(const float4*)wp, w1 = *(const float4*)(wp + 4);
                        val[0] += x0.x * w0.x; val[1] += x0.y * w0.y;
                        val[2] += x0.z * w0.z; val[3] += x0.w * w0.w;
                        val[4] += x1.x * w1.x; val[5] += x1.y * w1.y;
                        val[6] += x1.z * w1.z; val[7] += x1.w * w1.w;
                    }
                }
            }
        }
    }

    {
        const int s0 = 8 + (lane & 7);
        const int gi = (lane >> 3) - 1;
        #pragma unroll
        for (int i = 0; i < 8; i++) {
            float k0 = __shfl_sync(0xffffffffu, val[i], s0);
            float k1 = __shfl_sync(0xffffffffu, val[i], s0 + 8);
            float k2 = __shfl_sync(0xffffffffu, val[i], s0 + 16);
            if (lane >= 8) {
                float s = k0;
                if (gi >= 1) s += k1;
                if (gi >= 2) s += k2;
                val[i] = s;
            }
        }
    }

    float sum = 0.f;
    #pragma unroll
    for (int i = 0; i < 8; i++) sum += val[i];
    #pragma unroll
    for (int o = 16; o; o >>= 1) sum += __shfl_xor_sync(0xffffffffu, sum, o);
    float mean = sum * (1.0f / 256.0f);

    float ss = 0.f;
    #pragma unroll
    for (int i = 0; i < 8; i++) { float d = val[i] - mean; ss += d * d; }
    #pragma unroll
    for (int o = 16; o; o >>= 1) ss += __shfl_xor_sync(0xffffffffu, ss, o);
    float rstd = rsqrtf(ss * (1.0f / 256.0f) + LN_EPS);

    float4 g0 = *(const float4*)&g[c],  g1 = *(const float4*)&g[c + 4];
    float4 e0 = *(const float4*)&be[c], e1 = *(const float4*)&be[c + 4];
    *(float4*)&d_dwconv[(size_t)pix * DIM + c]     = make_float4(val[0], val[1], val[2], val[3]);
    *(float4*)&d_dwconv[(size_t)pix * DIM + c + 4] = make_float4(val[4], val[5], val[6], val[7]);

    float n[8];
    n[0]=(val[0]-mean)*rstd*g0.x+e0.x; n[1]=(val[1]-mean)*rstd*g0.y+e0.y;
    n[2]=(val[2]-mean)*rstd*g0.z+e0.z; n[3]=(val[3]-mean)*rstd*g0.w+e0.w;
    n[4]=(val[4]-mean)*rstd*g1.x+e1.x; n[5]=(val[5]-mean)*rstd*g1.y+e1.y;
    n[6]=(val[6]-mean)*rstd*g1.z+e1.z; n[7]=(val[7]-mean)*rstd*g1.w+e1.w;
    __half2 h0 = __floats2half2_rn(n[0], n[1]);
    __half2 h1 = __floats2half2_rn(n[2], n[3]);
    __half2 h2 = __floats2half2_rn(n[4], n[5]);
    __half2 h3 = __floats2half2_rn(n[6], n[7]);
    uint4 u;
    u.x = *(uint32_t*)&h0; u.y = *(uint32_t*)&h1;
    u.z = *(uint32_t*)&h2; u.w = *(uint32_t*)&h3;
    *(uint4*)&d_norm1h[(size_t)pix * DIM + c] = u;
}

// -------- fp16 GEMM v2: BK=64 halves (128B rows), 3-stage single-barrier ------
// xor-swizzled rows (chunk ^ (row&7)), 24 LDSM + 64 MMA per barrier.
// MODE 1: BN( +bias +add1 fp32 ) -> half (proj, PERBATCH)
// MODE 2: gelu(+bias) -> half (fc1)     MODE 3: +bias +add1 -> float (fc2)
// MODE 4: qkv: per-head l2norm; qTh/kTh fp16 transposed (smem-staged), vh dense
#define HG_BOFF  49152
#define HG_SMEM  98304

template<int KDIM, int MODE, bool PERBATCH>
__global__ void __launch_bounds__(256, 2)
hgemm(const __half* __restrict__ A,
      const __half* __restrict__ Bt,
      void* __restrict__ Cv, int ldc, int m_off,
      const float* __restrict__ bias, const float* __restrict__ add1,
      const float* __restrict__ bn_g, const float* __restrict__ bn_b,
      const float* __restrict__ bn_m, const float* __restrict__ bn_v)
{
    extern __shared__ char smem[];
    const uint32_t sb = (uint32_t)__cvta_generic_to_shared(smem);
    const int tid  = threadIdx.x;
    const int lane = tid & 31;
    const int w    = tid >> 5;
    const int wm   = w >> 2;
    const int wn   = w & 3;

    int m0, mrows;
    if (PERBATCH) {
        int batch = blockIdx.y / 25;
        int bt    = blockIdx.y % 25;
        m0 = batch * NPIX + bt * 128;
        mrows = min(128, NPIX - bt * 128);
    } else {
        m0 = m_off + blockIdx.y * 128; mrows = 128;
    }
    const int n0 = blockIdx.x * 128;
    const __half* Bp = PERBATCH ? (Bt + (size_t)(blockIdx.y / 25) * 65536) : Bt;

    float acc[4][4][4];
    #pragma unroll
    for (int mi = 0; mi < 4; mi++)
        #pragma unroll
        for (int ni = 0; ni < 4; ni++)
            #pragma unroll
            for (int q = 0; q < 4; q++) acc[mi][ni][q] = 0.f;

    auto load_stage = [&](int st) {
        int slot = st % 3;
        int k0 = st * 64;                 // halves
        #pragma unroll
        for (int i = 0; i < 4; i++) {
            int lin = tid + 256 * i;      // 0..1023
            int r = lin >> 3, ch = lin & 7;
            int rg = m0 + (r < mrows ? r : mrows - 1);
            cp_async16_s(sb + slot * 16384 + r * 128 + ((ch ^ (r & 7)) << 4),
                         A + (size_t)rg * KDIM + k0 + ch * 8);
        }
        #pragma unroll
        for (int i = 0; i < 4; i++) {
            int lin = tid + 256 * i;
            int r = lin >> 3, ch = lin & 7;
            cp_async16_s(sb + HG_BOFF + slot * 16384 + r * 128 + ((ch ^ (r & 7)) << 4),
                         Bp + (size_t)(n0 + r) * KDIM + k0 + ch * 8);
        }
        cp_commit();
    };

    const int KT = KDIM / 64;
    load_stage(0); load_stage(1);

    const int sx    = lane & 7;
    const int arow  = lane & 15;
    const int akoff = lane >> 4;
    const int brow  = ((lane >> 4) << 3) + (lane & 7);
    const int bkoff = (lane >> 3) & 1;

    for (int s = 0; s < KT; s++) {
        int slot = s % 3;
        if (s < KT - 1) asm volatile("cp.async.wait_group 1;\n" ::: "memory");
        else            asm volatile("cp.async.wait_group 0;\n" ::: "memory");
        __syncthreads();
        if (s + 2 < KT) load_stage(s + 2);

        uint32_t aBase = sb + slot * 16384 + (wm * 64) * 128;
        uint32_t bBase = sb + HG_BOFF + slot * 16384 + (wn * 32) * 128;

        #pragma unroll
        for (int ks = 0; ks < 4; ks++) {
            uint32_t a[4][4];
            #pragma unroll
            for (int mi = 0; mi < 4; mi++)
                ldsm_x4(a[mi], aBase + (mi * 16 + arow) * 128
                               + (((2 * ks + akoff) ^ sx) << 4));
            uint32_t bf[2][4];
            #pragma unroll
            for (int nj = 0; nj < 2; nj++)
                ldsm_x4(bf[nj], bBase + (nj * 16 + brow) * 128
                                + (((2 * ks + bkoff) ^ sx) << 4));
            #pragma unroll
            for (int mi = 0; mi < 4; mi++)
                #pragma unroll
                for (int ni = 0; ni < 4; ni++)
                    mma_f16(acc[mi][ni], a[mi],
                            bf[ni >> 1][(ni & 1) * 2], bf[ni >> 1][(ni & 1) * 2 + 1]);
        }
    }

    // ---- MODE 4 q/k path: l2norm + smem-staged transposed fp16 store ----
    if (MODE == 4 && n0 < 512) {
        float* sT = (float*)smem;             // [col 128][row 128], stride 132
        __syncthreads();
        #pragma unroll
        for (int mi = 0; mi < 4; mi++) {
            #pragma unroll
            for (int h = 0; h < 2; h++) {
                float ss = 0.f;
                #pragma unroll
                for (int ni = 0; ni < 4; ni++) {
                    float v0 = acc[mi][ni][2 * h], v1 = acc[mi][ni][2 * h + 1];
                    ss += v0 * v0 + v1 * v1;
                }
                ss += __shfl_xor_sync(0xffffffffu, ss, 1);
                ss += __shfl_xor_sync(0xffffffffu, ss, 2);
                float sc = rsqrtf(fmaxf(ss, L2_EPS));
                if (n0 < 256) sc *= SCALE_Q;

                int rowl = wm * 64 + mi * 16 + (lane >> 2) + h * 8;
                #pragma unroll
                for (int ni = 0; ni < 4; ni++) {
                    int dl = wn * 32 + ni * 8 + (lane & 3) * 2;
                    sT[dl * 132 + rowl]       = acc[mi][ni][2 * h] * sc;
                    sT[(dl + 1) * 132 + rowl] = acc[mi][ni][2 * h + 1] * sc;
                }
            }
        }
        __syncthreads();
        __half* dstT = (n0 < 256) ? d_qTh : d_kTh;
        #pragma unroll
        for (int i = 0; i < 16; i++) {
            int idx = tid + i * 256;
            int cl  = idx >> 5;
            int row = (idx & 31) * 4;
            int grow = m0 + row;
            int bb = grow / NPIX;
            int n  = grow - bb * NPIX;        // 4-run never straddles batch
            int gcol = n0 + cl;
            int head = (gcol & 255) >> 5;
            int d    = gcol & 31;
            float4 v4 = *(float4*)&sT[cl * 132 + row];
            __half2 p0 = __floats2half2_rn(v4.x, v4.y);
            __half2 p1 = __floats2half2_rn(v4.z, v4.w);
            uint2 u; u.x = *(uint32_t*)&p0; u.y = *(uint32_t*)&p1;
            *(uint2*)&dstT[((size_t)(bb * 8 + head) * 32 + d) * NPIX + n] = u;
        }
        return;
    }

    // ---- epilogue ----
    #pragma unroll
    for (int mi = 0; mi < 4; mi++) {
        #pragma unroll
        for (int h = 0; h < 2; h++) {
            int lr = wm * 64 + mi * 16 + (lane >> 2) + h * 8;
            if (PERBATCH && lr >= mrows) continue;
            size_t grow = (size_t)(m0 + lr);
            #pragma unroll
            for (int ni = 0; ni < 4; ni++) {
                float v0 = acc[mi][ni][2 * h], v1 = acc[mi][ni][2 * h + 1];
                if (MODE == 4) {
                    // v block (n0 >= 512): fp16 dense store, ldc = 256
                    int gc = (n0 - 512) + wn * 32 + ni * 8 + (lane & 3) * 2;
                    *(__half2*)((__half*)Cv + grow * ldc + gc) = __floats2half2_rn(v0, v1);
                    continue;
                }
                int gc = n0 + wn * 32 + ni * 8 + (lane & 3) * 2;
                if (MODE == 1) {
                    float2 ad = *(const float2*)&add1[grow * 256 + gc];
                    v0 += bias[gc]     + ad.x;
                    v1 += bias[gc + 1] + ad.y;
                    v0 = (v0 - bn_m[gc    ]) * rsqrtf(bn_v[gc    ] + BN_EPS) * bn_g[gc    ] + bn_b[gc    ];
                    v1 = (v1 - bn_m[gc + 1]) * rsqrtf(bn_v[gc + 1] + BN_EPS) * bn_g[gc + 1] + bn_b[gc + 1];
                    *(__half2*)((__half*)Cv + grow * ldc + gc) = __floats2half2_rn(v0, v1);
                } else if (MODE == 2) {
                    v0 += bias[gc];   v1 += bias[gc + 1];
                    v0 = 0.5f * v0 * (1.0f + erff(v0 * 0.70710678118654752f));
                    v1 = 0.5f * v1 * (1.0f + erff(v1 * 0.70710678118654752f));
                    *(__half2*)((__half*)Cv + grow * ldc + gc) = __floats2half2_rn(v0, v1);
                } else {
                    float2 ad = *(const float2*)&add1[grow * 256 + gc];
                    v0 += bias[gc]     + ad.x;
                    v1 += bias[gc + 1] + ad.y;
                    *(float2*)&((float*)Cv)[grow * ldc + gc] = make_float2(v0, v1);
                }
            }
        }
    }
}

// ------- attn split-K (fp16 mma): per (b,h,split) partial 32x32 q^T k --------
#define AS_STAGE 5120
#define AS_SMEM  15360

__global__ void __launch_bounds__(256) attn_split_kernel()
{
    extern __shared__ char smem[];
    const uint32_t sb = (uint32_t)__cvta_generic_to_shared(smem);
    const int bh = blockIdx.x;
    const int split = blockIdx.y;
    const int tid = threadIdx.x, lane = tid & 31, w = tid >> 5;
    const int wm = w >> 2, wn = w & 3;

    const __half* qT = d_qTh + (size_t)bh * 32 * NPIX + split * 224;
    const __half* kT = d_kTh + (size_t)bh * 32 * NPIX + split * 224;

    float c[4] = {0.f, 0.f, 0.f, 0.f};

    auto load_stage = [&](int st) {
        int slot = st % 3;
        int k0 = st * 32;                     // halves
        int op = tid >> 7;                    // 0 = q, 1 = k
        int rr = (tid >> 2) & 31;
        int ch = tid & 3;
        const __half* src = (op ? kT : qT) + (size_t)rr * NPIX + k0 + ch * 8;
        cp_async16_s(sb + slot * AS_STAGE + op * 2560 + rr * 80 + ch * 16, src);
        cp_commit();
    };

    const int KT = 7;                         // 224 / 32
    load_stage(0); load_stage(1);

    const int nj   = wn >> 1;
    const int nsel = (wn & 1) * 2;

    for (int s = 0; s < KT; s++) {
        int slot = s % 3;
        if (s < KT - 1) asm volatile("cp.async.wait_group 1;\n" ::: "memory");
        else            asm volatile("cp.async.wait_group 0;\n" ::: "memory");
        __syncthreads();
        if (s + 2 < KT) load_stage(s + 2);

        uint32_t aBase = sb + slot * AS_STAGE + (wm * 16) * 80;
        uint32_t bBase = sb + slot * AS_STAGE + 2560;
        #pragma unroll
        for (int ks = 0; ks < 2; ks++) {
            const int kc = ks * 2;
            uint32_t a[4], bf[4];
            ldsm_x4(a, aBase + (lane & 15) * 80 + (kc + (lane >> 4)) * 16);
            ldsm_x4(bf, bBase + (nj * 16 + ((lane >> 4) << 3) + (lane & 7)) * 80
                        + (kc + ((lane >> 3) & 1)) * 16);
            mma_f16(c, a, bf[nsel], bf[nsel + 1]);
        }
    }

    float* dst = d_attn_part + ((size_t)split * 128 + bh) * 1024;
    int row = wm * 16 + (lane >> 2);
    int col = wn * 8 + (lane & 3) * 2;
    dst[row * 32 + col]           = c[0];
    dst[row * 32 + col + 1]       = c[1];
    dst[(row + 8) * 32 + col]     = c[2];
    dst[(row + 8) * 32 + col + 1] = c[3];
}

// ------- attn finalize + softmax + wbT^h = (blockdiag attn @ proj_w)^T -------
__global__ void __launch_bounds__(1024) attn_wb_kernel(const float* __restrict__ proj_w)
{
    int bh = blockIdx.x;
    int b = bh >> 3, h = bh & 7;
    int tid = threadIdx.x;
    int e = tid & 31, d = tid >> 5;

    __shared__ float sA[32][33];
    __shared__ float sW[32][256];

    float acc = 0.f;
    #pragma unroll
    for (int s = 0; s < NSPLIT; s++)
        acc += d_attn_part[((size_t)s * 128 + bh) * 1024 + d * 32 + e];

    float m = acc;
    #pragma unroll
    for (int o = 16; o; o >>= 1) m = fmaxf(m, __shfl_xor_sync(0xffffffffu, m, o));
    float ex = expf(acc - m);
    float sum = ex;
    #pragma unroll
    for (int o = 16; o; o >>= 1) sum += __shfl_xor_sync(0xffffffffu, sum, o);
    sA[d][e] = ex / sum;

    #pragma unroll
    for (int idx = tid; idx < 8192; idx += 1024)
        sW[idx >> 8][idx & 255] = proj_w[(h * 32 + (idx >> 8)) * 256 + (idx & 255)];
    __syncthreads();

    #pragma unroll
    for (int idx = tid; idx < 8192; idx += 1024) {
        int d2 = idx & 31, c = idx >> 5;
        float s = 0.f;
        #pragma unroll
        for (int ee = 0; ee < 32; ee++) s += sA[d2][ee] * sW[ee][c];
        d_wbTh[(size_t)b * 65536 + c * 256 + h * 32 + d2] = __float2half(s);
    }
}

// ---------------- launch ------------------------------------------------------
extern "C" void kernel_launch(void* const* d_in, const int* in_sizes, int n_in,
                              void* d_out, int out_size)
{
    const float* x        = (const float*)d_in[0];
    const float* dw_kernel= (const float*)d_in[1];
    const float* dw_bias  = (const float*)d_in[2];
    const float* ln_gamma = (const float*)d_in[3];
    const float* ln_beta  = (const float*)d_in[4];
    const float* qkv_w    = (const float*)d_in[5];
    const float* proj_w   = (const float*)d_in[6];
    const float* proj_b   = (const float*)d_in[7];
    const float* bn_gamma = (const float*)d_in[8];
    const float* bn_beta  = (const float*)d_in[9];
    const float* bn_mean  = (const float*)d_in[10];
    const float* bn_var   = (const float*)d_in[11];
    const float* fc1_w    = (const float*)d_in[12];
    const float* fc1_b    = (const float*)d_in[13];
    const float* fc2_w    = (const float*)d_in[14];
    const float* fc2_b    = (const float*)d_in[15];
    float* out = (float*)d_out;

    float  *p_dwconv;
    __half *p_norm1h, *p_vh, *p_wbTh, *p_mergedh, *p_h1h, *p_qkvTh, *p_fc1T, *p_fc2T;
    cudaGetSymbolAddress((void**)&p_dwconv,  d_dwconv);
    cudaGetSymbolAddress((void**)&p_norm1h,  d_norm1h);
    cudaGetSymbolAddress((void**)&p_vh,      d_vh);
    cudaGetSymbolAddress((void**)&p_wbTh,    d_wbTh);
    cudaGetSymbolAddress((void**)&p_mergedh, d_mergedh);
    cudaGetSymbolAddress((void**)&p_h1h,     d_h1h);
    cudaGetSymbolAddress((void**)&p_qkvTh,   d_qkvTh);
    cudaGetSymbolAddress((void**)&p_fc1T,    d_fc1T);
    cudaGetSymbolAddress((void**)&p_fc2T,    d_fc2T);

    cudaFuncSetAttribute(hgemm<256, 4, false>,
                         cudaFuncAttributeMaxDynamicSharedMemorySize, HG_SMEM);
    cudaFuncSetAttribute(hgemm<256, 1, true>,
                         cudaFuncAttributeMaxDynamicSharedMemorySize, HG_SMEM);
    cudaFuncSetAttribute(hgemm<256, 2, false>,
                         cudaFuncAttributeMaxDynamicSharedMemorySize, HG_SMEM);
    cudaFuncSetAttribute(hgemm<1024, 3, false>,
                         cudaFuncAttributeMaxDynamicSharedMemorySize, HG_SMEM);

    // 1) transpose weights (all fp16)
    transpose3_kernel<<<dim3(32, 32, 3), 256>>>(qkv_w, fc1_w, fc2_w);

    // 2) dwconv + cumsum + LN (dwconv fp32, norm1 fp16)
    dwln_kernel<<<NTOK / 8, 256>>>(x, dw_kernel, dw_bias, ln_gamma, ln_beta);

    // 3) qkv GEMM (fp16, BK=64), two half-M launches; qTh/kTh/vh fp16 outputs
    hgemm<256, 4, false><<<dim3(6, 196), 256, HG_SMEM>>>(
        p_norm1h, p_qkvTh, p_vh, 256, 0,
        nullptr, nullptr, nullptr, nullptr, nullptr, nullptr);
    hgemm<256, 4, false><<<dim3(6, 196), 256, HG_SMEM>>>(
        p_norm1h, p_qkvTh, p_vh, 256, NTOK / 2,
        nullptr, nullptr, nullptr, nullptr, nullptr, nullptr);

    // 4) attn partials (fp16 mma, split-K x14)
    attn_split_kernel<<<dim3(BATCH * HEADS, NSPLIT), 256, AS_SMEM>>>();

    // 5) softmax + wbT (fp16)
    attn_wb_kernel<<<BATCH * HEADS, 1024>>>(proj_w);

    // 6) merged = BN( v @ W_b + proj_b + dwconv ) -> fp16   (fp16 GEMM, per-batch)
    hgemm<256, 1, true><<<dim3(2, BATCH * 25), 256, HG_SMEM>>>(
        p_vh, p_wbTh, p_mergedh, 256, 0,
        proj_b, p_dwconv, bn_gamma, bn_beta, bn_mean, bn_var);

    // 7) h1 = gelu(merged @ fc1_w + fc1_b) -> fp16
    hgemm<256, 2, false><<<dim3(8, NTOK / 128), 256, HG_SMEM>>>(
        p_mergedh, p_fc1T, p_h1h, 1024, 0,
        fc1_b, nullptr, nullptr, nullptr, nullptr, nullptr);

    // 8) out = h1 @ fc2_w + fc2_b + x -> fp32
    hgemm<1024, 3, false><<<dim3(2, NTOK / 128), 256, HG_SMEM>>>(
        p_h1h, p_fc2T, out, 256, 0,
        fc2_b, x, nullptr, nullptr, nullptr, nullptr);
}